// round 7
// baseline (speedup 1.0000x reference)
#include <cuda_runtime.h>
#include <cuda_fp16.h>
#include <math.h>

#define NC   128
#define WW   512
#define HH   512
#define NHW  (HH*WW)
#define MAXN 10000
#define GRID 592          // 4 blocks/SM x 148 SMs — co-residency guaranteed at <=64 regs

// ---------------- persistent device state ----------------
__device__ __align__(16) __half g_fqH[NC * NHW];  // (pixel, channel) layout, fp16
__device__ float  g_p2init[2 * MAXN];
__device__ double g_acc[29];    // [0..20] Hess uptri, [21..26] Grad, [27] cost, [28] count
__device__ double g_tacc[2];    // trial cost sum, count
__device__ double g_costbest;
__device__ float  g_R[9], g_t[3], g_Rn[9], g_tn[3];
__device__ float  g_lam, g_jac[6];
__device__ unsigned int g_barrier, g_gen;

__constant__ int c_hi[21] = {0,0,0,0,0,0, 1,1,1,1,1, 2,2,2,2, 3,3,3, 4,4, 5};
__constant__ int c_hj[21] = {0,1,2,3,4,5, 1,2,3,4,5, 2,3,4,5, 3,4,5, 4,5, 5};

// ---------------- helpers ----------------
__device__ __forceinline__ void unpack8(uint4 raw, float* p) {
    const __half2* h = (const __half2*)&raw;
#pragma unroll
    for (int j = 0; j < 4; j++) {
        float2 f = __half22float2(h[j]);
        p[2 * j]     = f.x;
        p[2 * j + 1] = f.y;
    }
}

template <int NV>
__device__ __forceinline__ void halfReduce(float* v) {
#pragma unroll
    for (int off = 8; off > 0; off >>= 1)
#pragma unroll
        for (int i = 0; i < NV; i++) v[i] += __shfl_xor_sync(0xffffffffu, v[i], off);
}

__device__ __forceinline__ float selJ0(int k, float fxz, float fxz2, float x, float y, float z) {
    switch (k) {
        case 0: return fxz;
        case 1: return 0.0f;
        case 2: return fxz2;
        case 3: return fxz2 * y;
        case 4: return fxz * z - fxz2 * x;
        default: return -fxz * y;
    }
}
__device__ __forceinline__ float selJ1(int k, float fyz, float fyz2, float x, float y, float z) {
    switch (k) {
        case 0: return 0.0f;
        case 1: return fyz;
        case 2: return fyz2;
        case 3: return -fyz * z + fyz2 * y;
        case 4: return -fyz2 * x;
        default: return fyz * x;
    }
}

__device__ __forceinline__ bool inImage(float px, float py) {
    return (px >= 1.0f) && (px < 511.0f) && (py >= 1.0f) && (py < 511.0f);
}

// bilinear footprint in uint4 (=8 half-channels) units: 16 per pixel
__device__ __forceinline__ void bilin4(float px, float py, int* o, float* w) {
    float x0f = fminf(fmaxf(floorf(px), 0.0f), 511.0f);
    float y0f = fminf(fmaxf(floorf(py), 0.0f), 511.0f);
    float x1f = fminf(x0f + 1.0f, 511.0f);
    float y1f = fminf(y0f + 1.0f, 511.0f);
    float wx = px - x0f, wy = py - y0f;
    int x0 = (int)x0f, x1 = (int)x1f, y0 = (int)y0f, y1 = (int)y1f;
    o[0] = (y0 * WW + x0) * 16;
    o[1] = (y0 * WW + x1) * 16;
    o[2] = (y1 * WW + x0) * 16;
    o[3] = (y1 * WW + x1) * 16;
    w[0] = (1.0f - wx) * (1.0f - wy);
    w[1] = wx * (1.0f - wy);
    w[2] = (1.0f - wx) * wy;
    w[3] = wx * wy;
}

// grid-wide barrier: all blocks co-resident by construction (grid=592, <=64 regs)
__device__ __forceinline__ void gridSync() {
    __syncthreads();
    if (threadIdx.x == 0) {
        __threadfence();
        unsigned int gen = *(volatile unsigned int*)&g_gen;
        unsigned int t = atomicAdd(&g_barrier, 1u);
        if (t == gridDim.x - 1) {
            g_barrier = 0;
            __threadfence();
            atomicAdd(&g_gen, 1u);
        } else {
            while (*(volatile unsigned int*)&g_gen == gen) __nanosleep(64);
        }
        __threadfence();
    }
    __syncthreads();
}

// ---------------- init ----------------
__global__ void k_init(const float* __restrict__ R0, const float* __restrict__ t0) {
    int i = threadIdx.x;
    if (i < 9) { g_R[i] = R0[i]; g_Rn[i] = R0[i]; }
    if (i < 3) { g_t[i] = t0[i]; g_tn[i] = t0[i]; }
    if (i == 0) {
        g_lam = 0.01f; g_costbest = -1e300;
        g_tacc[0] = 0.0; g_tacc[1] = 1.0;
        g_barrier = 0u; g_gen = 0u;
    }
    if (i < 29) g_acc[i] = 0.0;
}

// ---------------- transpose (C,H,W) f32 -> (H*W, C) f16 ----------------
__global__ void __launch_bounds__(256) k_transpose(const float* __restrict__ fq) {
    __shared__ float sh[64][NC + 1];
    int pix0 = blockIdx.x * 64;
    int tid = threadIdx.x;
    int px = tid & 63;
    int crow = tid >> 6;
#pragma unroll
    for (int cb = 0; cb < NC; cb += 4) {
        int c = cb + crow;
        sh[px][c] = fq[c * NHW + pix0 + px];
    }
    __syncthreads();
    int cpair = tid & 63;
    int prow = tid >> 6;
    __half2* out2 = (__half2*)g_fqH;
#pragma unroll
    for (int pb = 0; pb < 64; pb += 4) {
        int p = pb + prow;
        __half2 h = __floats2half2_rn(sh[p][2 * cpair], sh[p][2 * cpair + 1]);
        out2[(size_t)(pix0 + p) * 64 + cpair] = h;
    }
}

// ---------------- fp32 solve (single thread, between grid syncs) ----------------
__device__ void do_solve(int iter) {
    volatile double* acc = g_acc;
    if (iter > 0) {
        double cn = g_tacc[0] / g_tacc[1];
        bool a = (cn <= g_costbest);
        float l = g_lam * (a ? 0.1f : 10.0f);
        g_lam = fminf(fmaxf(l, 1e-8f), 1e4f);
        if (a) {
#pragma unroll
            for (int i = 0; i < 9; i++) g_R[i] = g_Rn[i];
#pragma unroll
            for (int i = 0; i < 3; i++) g_t[i] = g_tn[i];
            g_costbest = cn;
        }
    } else {
        g_costbest = acc[27] / acc[28];
    }

    float jac[6];
    if (iter == 0) {
        const int dix[6] = {0, 6, 11, 15, 18, 20};
#pragma unroll
        for (int i = 0; i < 6; i++) {
            jac[i] = 1.0f / (1.0f + sqrtf((float)acc[dix[i]]));
            g_jac[i] = jac[i];
        }
    } else {
#pragma unroll
        for (int i = 0; i < 6; i++) jac[i] = g_jac[i];
    }

    float A[6][7];
    {
        int idx = 0;
#pragma unroll
        for (int i = 0; i < 6; i++)
#pragma unroll
            for (int j = i; j < 6; j++) {
                float v = (float)acc[idx++] * jac[i] * jac[j];
                A[i][j] = v;
                A[j][i] = v;
            }
    }
    float lam = g_lam;
#pragma unroll
    for (int i = 0; i < 6; i++) {
        float d = A[i][i];
        A[i][i] = d + (d + 1e-9f) * lam;
        A[i][6] = -(float)acc[21 + i] * jac[i];
    }
    for (int col = 0; col < 6; col++) {
        int piv = col;
        float best = fabsf(A[col][col]);
        for (int r = col + 1; r < 6; r++) {
            float v = fabsf(A[r][col]);
            if (v > best) { best = v; piv = r; }
        }
        if (piv != col)
            for (int j = 0; j < 7; j++) { float t = A[col][j]; A[col][j] = A[piv][j]; A[piv][j] = t; }
        float ip = 1.0f / A[col][col];
        for (int r = col + 1; r < 6; r++) {
            float f = A[r][col] * ip;
            for (int j = col; j < 7; j++) A[r][j] -= f * A[col][j];
        }
    }
    float x[6];
#pragma unroll
    for (int i = 5; i >= 0; i--) {
        float v = A[i][6];
#pragma unroll
        for (int j = 0; j < 6; j++)
            if (j > i) v -= A[i][j] * x[j];
        x[i] = v / A[i][i];
    }
    float delta[6];
#pragma unroll
    for (int i = 0; i < 6; i++) delta[i] = x[i] * jac[i];

    float w0 = delta[3], w1 = delta[4], w2 = delta[5];
    float th2 = w0 * w0 + w1 * w1 + w2 * w2;
    float th = sqrtf(th2);
    float Ac, Bc;
    if (th < 1e-7f) { Ac = 1.0f; Bc = 0.5f; }
    else            { Ac = sinf(th) / th; Bc = (1.0f - cosf(th)) / th2; }
    float Wm[9] = {0.0f, -w2, w1, w2, 0.0f, -w0, -w1, w0, 0.0f};
    float W2[9];
#pragma unroll
    for (int i = 0; i < 3; i++)
#pragma unroll
        for (int j = 0; j < 3; j++) {
            float s2 = 0.0f;
#pragma unroll
            for (int k = 0; k < 3; k++) s2 += Wm[i * 3 + k] * Wm[k * 3 + j];
            W2[i * 3 + j] = s2;
        }
    float dr[9];
#pragma unroll
    for (int i = 0; i < 9; i++)
        dr[i] = ((i % 4) == 0 ? 1.0f : 0.0f) + Ac * Wm[i] + Bc * W2[i];

    float Rl[9], Tl[3];
#pragma unroll
    for (int i = 0; i < 9; i++) Rl[i] = g_R[i];
#pragma unroll
    for (int i = 0; i < 3; i++) Tl[i] = g_t[i];
#pragma unroll
    for (int i = 0; i < 3; i++) {
#pragma unroll
        for (int j = 0; j < 3; j++) {
            float s2 = 0.0f;
#pragma unroll
            for (int k = 0; k < 3; k++) s2 += dr[i * 3 + k] * Rl[k * 3 + j];
            g_Rn[i * 3 + j] = s2;
        }
        g_tn[i] = dr[i * 3] * Tl[0] + dr[i * 3 + 1] * Tl[1] + dr[i * 3 + 2] * Tl[2] + delta[i];
    }
#pragma unroll
    for (int i = 0; i < 29; i++) g_acc[i] = 0.0;
    g_tacc[0] = 0.0;
    g_tacc[1] = 0.0;
}

// accumulator slot value (0..28) for one point
__device__ __forceinline__ float valForIdx(int idx, float Mxx, float Mxy, float Myy,
                                           float g2x, float g2y, float errsq,
                                           float fxz, float fxz2, float fyz, float fyz2,
                                           float x_, float y_, float d) {
    if (idx < 21) {
        int i = c_hi[idx], j = c_hj[idx];
        float a0 = selJ0(i, fxz, fxz2, x_, y_, d);
        float a1 = selJ1(i, fyz, fyz2, x_, y_, d);
        float b0 = selJ0(j, fxz, fxz2, x_, y_, d);
        float b1 = selJ1(j, fyz, fyz2, x_, y_, d);
        float u  = Mxx * a0 + Mxy * a1;
        float vv = Mxy * a0 + Myy * a1;
        return u * b0 + vv * b1;
    } else if (idx < 27) {
        int j = idx - 21;
        float b0 = selJ0(j, fxz, fxz2, x_, y_, d);
        float b1 = selJ1(j, fyz, fyz2, x_, y_, d);
        return g2x * b0 + g2y * b1;
    } else if (idx == 27) {
        return errsq;
    }
    return 1.0f;
}

// ---------------- one full LM iteration: main -> solve -> trial (-> final) ----------------
__global__ void __launch_bounds__(256, 4) k_iter(const float* __restrict__ p3D,
                                                 const float* __restrict__ fref,
                                                 const float* __restrict__ Km,
                                                 int N, int iter, float* __restrict__ out) {
    int tid = threadIdx.x, lane = tid & 31, warp = tid >> 5;
    int hl = lane & 15, side = lane >> 4;
    int wid0 = blockIdx.x * 8 + warp;
    const int PTSTRIDE = GRID * 16;   // 8 warps/block * 2 pts/warp
    float fx = Km[0], fy = Km[4], cx = Km[2], cy = Km[5];
    const uint4* __restrict__ B = (const uint4*)g_fqH;
    const float4* __restrict__ F4p = (const float4*)fref;

    __shared__ double sred[8][29];

    // ================= phase A: LM accumulation at current pose =================
    {
        double cn = g_tacc[0] / g_tacc[1];
        bool accPrev = (cn <= g_costbest);
        float R[9], T[3];
#pragma unroll
        for (int i = 0; i < 9; i++) R[i] = accPrev ? g_Rn[i] : g_R[i];
#pragma unroll
        for (int i = 0; i < 3; i++) T[i] = accPrev ? g_tn[i] : g_t[i];

        double a0 = 0.0, a1 = 0.0;
        for (int pt = 2 * wid0 + side; pt < N; pt += PTSTRIDE) {
            float Px = p3D[3 * pt], Py = p3D[3 * pt + 1], Pz = p3D[3 * pt + 2];
            float x_ = R[0] * Px + R[1] * Py + R[2] * Pz + T[0];
            float y_ = R[3] * Px + R[4] * Py + R[5] * Pz + T[1];
            float d  = R[6] * Px + R[7] * Py + R[8] * Pz + T[2];
            float izd0 = 1.0f / d;
            float px = x_ * izd0 * fx + cx;
            float py = y_ * izd0 * fy + cy;
            if (iter == 0 && hl == 0) { g_p2init[2 * pt] = px; g_p2init[2 * pt + 1] = py; }
            bool valid = inImage(px, py);
            if (!valid) { px = 256.0f; py = 256.0f; d = 1.0f; }
            float izd = 1.0f / d;

            float x0f = floorf(px), y0f = floorf(py);
            float wx = px - x0f, wy = py - y0f;
            int x0 = (int)x0f, x1 = x0 + 1, y0 = (int)y0f, y1 = y0 + 1;
            int colo[4] = {(x0 - 1) * 16, x0 * 16, x1 * 16, (x1 < 511 ? x1 + 1 : 511) * 16};
            int rowo[4] = {(y0 - 1) * (WW * 16), y0 * (WW * 16), y1 * (WW * 16),
                           (y1 < 511 ? y1 + 1 : 511) * (WW * 16)};

            // separable sobel x bilinear weights: wgx=Ay[i]Bx[j]/8, wgy=By[i]Ax[j]/8
            float Ax[4]  = {1.0f - wx, 2.0f - wx, 1.0f + wx, wx};
            float Bx[4]  = {-(1.0f - wx), -wx, 1.0f - wx, wx};
            float Ay8[4] = {(1.0f - wy) * 0.125f, (2.0f - wy) * 0.125f,
                            (1.0f + wy) * 0.125f, wy * 0.125f};
            float By8[4] = {-(1.0f - wy) * 0.125f, -wy * 0.125f,
                            (1.0f - wy) * 0.125f, wy * 0.125f};
            float fyw0 = 1.0f - wy, fxw0 = 1.0f - wx;

            float f8[8], gx8[8], gy8[8];
#pragma unroll
            for (int j = 0; j < 8; j++) { f8[j] = 0.0f; gx8[j] = 0.0f; gy8[j] = 0.0f; }
#pragma unroll
            for (int i = 0; i < 4; i++) {
                float rx[8], ra[8];
#pragma unroll
                for (int j = 0; j < 8; j++) { rx[j] = 0.0f; ra[j] = 0.0f; }
#pragma unroll
                for (int j = 0; j < 4; j++) {
                    uint4 raw = __ldg(&B[rowo[i] + colo[j] + hl]);
                    float p[8];
                    unpack8(raw, p);
#pragma unroll
                    for (int c = 0; c < 8; c++) {
                        rx[c] += Bx[j] * p[c];
                        ra[c] += Ax[j] * p[c];
                    }
                    if ((i == 1 || i == 2) && (j == 1 || j == 2)) {
                        float wcf = ((j == 1) ? fxw0 : wx) * ((i == 1) ? fyw0 : wy);
#pragma unroll
                        for (int c = 0; c < 8; c++) f8[c] += wcf * p[c];
                    }
                }
#pragma unroll
                for (int c = 0; c < 8; c++) {
                    gx8[c] += Ay8[i] * rx[c];
                    gy8[c] += By8[i] * ra[c];
                }
            }
            float r8[8];
            {
                float4 rra = __ldg(&F4p[pt * 32 + 2 * hl]);
                float4 rrb = __ldg(&F4p[pt * 32 + 2 * hl + 1]);
                r8[0] = rra.x; r8[1] = rra.y; r8[2] = rra.z; r8[3] = rra.w;
                r8[4] = rrb.x; r8[5] = rrb.y; r8[6] = rrb.z; r8[7] = rrb.w;
            }

            float s[10];
#pragma unroll
            for (int i = 0; i < 10; i++) s[i] = 0.0f;
#pragma unroll
            for (int j = 0; j < 8; j++) {
                s[0] += f8[j] * f8[j];   s[1] += f8[j] * gx8[j];  s[2] += f8[j] * gy8[j];
                s[3] += gx8[j] * gx8[j]; s[4] += gx8[j] * gy8[j]; s[5] += gy8[j] * gy8[j];
                s[6] += gx8[j] * r8[j];  s[7] += gy8[j] * r8[j];  s[8] += f8[j] * r8[j];
                s[9] += r8[j] * r8[j];
            }
            halfReduce<10>(s);

            float norm  = fmaxf(sqrtf(s[0]), 1e-12f);
            float rnorm = fmaxf(sqrtf(s[9]), 1e-12f);
            float inorm = 1.0f / norm, irn = 1.0f / rnorm;
            float projx = s[1] * inorm, projy = s[2] * inorm;
            float nf2 = s[0] * inorm * inorm;
            float sc  = s[8] * inorm * irn;
            float in2 = inorm * inorm;
            float fac = 2.0f - nf2;
            float Mxx = (s[3] - projx * projx * fac) * in2;
            float Mxy = (s[4] - projx * projy * fac) * in2;
            float Myy = (s[5] - projy * projy * fac) * in2;
            float coef = 1.0f - nf2 + sc;
            float g2x = (projx * coef - s[6] * irn) * inorm;
            float g2y = (projy * coef - s[7] * irn) * inorm;
            float errsq = nf2 - 2.0f * sc + s[9] * irn * irn;

            float fxz = fx * izd, fxz2 = -fx * x_ * izd * izd;
            float fyz = fy * izd, fyz2 = -fy * y_ * izd * izd;
            float vf = valid ? 1.0f : 0.0f;

            a0 += (double)(vf * valForIdx(hl, Mxx, Mxy, Myy, g2x, g2y, errsq,
                                          fxz, fxz2, fyz, fyz2, x_, y_, d));
            if (hl < 13)
                a1 += (double)(vf * valForIdx(hl + 16, Mxx, Mxy, Myy, g2x, g2y, errsq,
                                              fxz, fxz2, fyz, fyz2, x_, y_, d));
        }
        a0 += __shfl_down_sync(0xffffffffu, a0, 16);
        a1 += __shfl_down_sync(0xffffffffu, a1, 16);
        if (lane < 16) sred[warp][lane] = a0;
        if (lane < 13) sred[warp][16 + lane] = a1;
        __syncthreads();
        if (warp == 0 && lane < 29) {
            double t2 = 0.0;
#pragma unroll
            for (int w2i = 0; w2i < 8; w2i++) t2 += sred[w2i][lane];
            atomicAdd(&g_acc[lane], t2);
        }
    }

    gridSync();
    if (blockIdx.x == 0 && tid == 0) do_solve(iter);
    gridSync();

    // ================= phase B: trial cost at candidate pose =================
    {
        float R[9], T[3];
#pragma unroll
        for (int i = 0; i < 9; i++) R[i] = *(volatile float*)&g_Rn[i];
#pragma unroll
        for (int i = 0; i < 3; i++) T[i] = *(volatile float*)&g_tn[i];

        double eD = 0.0, eC = 0.0;
        for (int pt = 2 * wid0 + side; pt < N; pt += PTSTRIDE) {
            float Px = p3D[3 * pt], Py = p3D[3 * pt + 1], Pz = p3D[3 * pt + 2];
            float x_ = R[0] * Px + R[1] * Py + R[2] * Pz + T[0];
            float y_ = R[3] * Px + R[4] * Py + R[5] * Pz + T[1];
            float d  = R[6] * Px + R[7] * Py + R[8] * Pz + T[2];
            float izd = 1.0f / d;
            float px = x_ * izd * fx + cx;
            float py = y_ * izd * fy + cy;
            bool valid = inImage(px, py);
            if (!valid) { px = 256.0f; py = 256.0f; }

            int o[4]; float w[4];
            bilin4(px, py, o, w);
            float f8[8];
#pragma unroll
            for (int j = 0; j < 8; j++) f8[j] = 0.0f;
#pragma unroll
            for (int k = 0; k < 4; k++) {
                uint4 raw = __ldg(&B[o[k] + hl]);
                float p[8];
                unpack8(raw, p);
#pragma unroll
                for (int j = 0; j < 8; j++) f8[j] += w[k] * p[j];
            }
            float r8[8];
            {
                float4 rra = __ldg(&F4p[pt * 32 + 2 * hl]);
                float4 rrb = __ldg(&F4p[pt * 32 + 2 * hl + 1]);
                r8[0] = rra.x; r8[1] = rra.y; r8[2] = rra.z; r8[3] = rra.w;
                r8[4] = rrb.x; r8[5] = rrb.y; r8[6] = rrb.z; r8[7] = rrb.w;
            }
            float s[3] = {0.0f, 0.0f, 0.0f};
#pragma unroll
            for (int j = 0; j < 8; j++) {
                s[0] += f8[j] * f8[j];
                s[1] += f8[j] * r8[j];
                s[2] += r8[j] * r8[j];
            }
            halfReduce<3>(s);
            if (hl == 0) {
                float inorm = 1.0f / fmaxf(sqrtf(s[0]), 1e-12f);
                float irn   = 1.0f / fmaxf(sqrtf(s[2]), 1e-12f);
                float errsq = s[0] * inorm * inorm - 2.0f * s[1] * inorm * irn + s[2] * irn * irn;
                float vf = valid ? 1.0f : 0.0f;
                eD += (double)(errsq * vf);
                eC += (double)vf;
            }
        }
        eD += __shfl_down_sync(0xffffffffu, eD, 16);
        eC += __shfl_down_sync(0xffffffffu, eC, 16);
        __syncthreads();   // sred reuse safety
        if (lane == 0) { sred[warp][0] = eD; sred[warp][1] = eC; }
        __syncthreads();
        if (tid == 0) {
            double a = 0.0, b = 0.0;
#pragma unroll
            for (int i = 0; i < 8; i++) { a += sred[i][0]; b += sred[i][1]; }
            atomicAdd(&g_tacc[0], a);
            atomicAdd(&g_tacc[1], b);
        }
    }

    // ================= phase C (last iteration only): final costs + pose out =================
    if (iter == 7) {
        gridSync();
        double cn = *(volatile double*)&g_tacc[0] / *(volatile double*)&g_tacc[1];
        bool accPrev = (cn <= *(volatile double*)&g_costbest);
        float R[9], T[3];
#pragma unroll
        for (int i = 0; i < 9; i++)
            R[i] = accPrev ? *(volatile float*)&g_Rn[i] : *(volatile float*)&g_R[i];
#pragma unroll
        for (int i = 0; i < 3; i++)
            T[i] = accPrev ? *(volatile float*)&g_tn[i] : *(volatile float*)&g_t[i];

        if (blockIdx.x == 0 && tid == 0) {
#pragma unroll
            for (int i = 0; i < 9; i++) out[i] = R[i];
#pragma unroll
            for (int i = 0; i < 3; i++) out[9 + i] = T[i];
        }
        const float NANF = __int_as_float(0x7fc00000);

        for (int pt = 2 * wid0 + side; pt < N; pt += PTSTRIDE) {
            float pix = g_p2init[2 * pt], piy = g_p2init[2 * pt + 1];
            float Px = p3D[3 * pt], Py = p3D[3 * pt + 1], Pz = p3D[3 * pt + 2];
            float x_ = R[0] * Px + R[1] * Py + R[2] * Pz + T[0];
            float y_ = R[3] * Px + R[4] * Py + R[5] * Pz + T[1];
            float d  = R[6] * Px + R[7] * Py + R[8] * Pz + T[2];
            float izd = 1.0f / d;
            float pfx = x_ * izd * fx + cx;
            float pfy = y_ * izd * fy + cy;

            bool vi = inImage(pix, piy);
            bool vfv = inImage(pfx, pfy);
            float pixc = vi ? pix : 256.0f, piyc = vi ? piy : 256.0f;
            float pfxc = vfv ? pfx : 256.0f, pfyc = vfv ? pfy : 256.0f;

            int oi[4], of_[4];
            float wi[4], wf[4];
            bilin4(pixc, piyc, oi, wi);
            bilin4(pfxc, pfyc, of_, wf);

            float fi8[8], ff8[8];
#pragma unroll
            for (int j = 0; j < 8; j++) { fi8[j] = 0.0f; ff8[j] = 0.0f; }
#pragma unroll
            for (int k = 0; k < 4; k++) {
                uint4 rawi = __ldg(&B[oi[k] + hl]);
                uint4 rawf = __ldg(&B[of_[k] + hl]);
                float pi[8], pf[8];
                unpack8(rawi, pi);
                unpack8(rawf, pf);
#pragma unroll
                for (int j = 0; j < 8; j++) {
                    fi8[j] += wi[k] * pi[j];
                    ff8[j] += wf[k] * pf[j];
                }
            }
            float r8[8];
            {
                float4 rra = __ldg(&F4p[pt * 32 + 2 * hl]);
                float4 rrb = __ldg(&F4p[pt * 32 + 2 * hl + 1]);
                r8[0] = rra.x; r8[1] = rra.y; r8[2] = rra.z; r8[3] = rra.w;
                r8[4] = rrb.x; r8[5] = rrb.y; r8[6] = rrb.z; r8[7] = rrb.w;
            }
            float s[5] = {0, 0, 0, 0, 0};
#pragma unroll
            for (int j = 0; j < 8; j++) {
                s[0] += fi8[j] * fi8[j];
                s[1] += fi8[j] * r8[j];
                s[2] += ff8[j] * ff8[j];
                s[3] += ff8[j] * r8[j];
                s[4] += r8[j] * r8[j];
            }
            halfReduce<5>(s);
            if (hl == 0) {
                float irn = 1.0f / fmaxf(sqrtf(s[4]), 1e-12f);
                float ini = 1.0f / fmaxf(sqrtf(s[0]), 1e-12f);
                float inf_ = 1.0f / fmaxf(sqrtf(s[2]), 1e-12f);
                float rr = s[4] * irn * irn;
                float ci = rr - 2.0f * s[1] * ini * irn + s[0] * ini * ini;
                float cf = rr - 2.0f * s[3] * inf_ * irn + s[2] * inf_ * inf_;
                out[12 + pt]     = vi  ? ci : NANF;
                out[12 + N + pt] = vfv ? cf : NANF;
            }
        }
    }
}

// ---------------- launch ----------------
extern "C" void kernel_launch(void* const* d_in, const int* in_sizes, int n_in,
                              void* d_out, int out_size) {
    const float* p3D  = (const float*)d_in[0];
    const float* fref = (const float*)d_in[1];
    const float* fq   = (const float*)d_in[2];
    const float* Km   = (const float*)d_in[3];
    const float* R0   = (const float*)d_in[4];
    const float* t0   = (const float*)d_in[5];
    float* out = (float*)d_out;
    int N = in_sizes[0] / 3;
    if (N > MAXN) N = MAXN;

    k_init<<<1, 32>>>(R0, t0);
    k_transpose<<<NHW / 64, 256>>>(fq);
    for (int i = 0; i < 8; i++)
        k_iter<<<GRID, 256>>>(p3D, fref, Km, N, i, out);
}

// round 8
// speedup vs baseline: 1.5467x; 1.5467x over previous
#include <cuda_runtime.h>
#include <cuda_fp16.h>
#include <math.h>

#define NC   128
#define WW   512
#define HH   512
#define NHW  (HH*WW)
#define MAXN 10000

// ---------------- persistent device state ----------------
__device__ __align__(16) __half g_fqH[NC * NHW];  // (pixel, channel) layout, fp16
__device__ float  g_p2init[2 * MAXN];
__device__ double g_acc[29];    // [0..20] Hess uptri, [21..26] Grad, [27] cost, [28] count
__device__ double g_Hsav[27];   // H/G snapshot at last accepted pose
__device__ double g_tacc[2];    // final trial cost sum, count
__device__ double g_costbest;
__device__ float  g_R[9], g_t[3];     // accepted pose
__device__ float  g_Rn[9], g_tn[3];   // eval / candidate pose
__device__ float  g_lam, g_jac[6];
__device__ unsigned int g_count;

__constant__ int c_hi[21] = {0,0,0,0,0,0, 1,1,1,1,1, 2,2,2,2, 3,3,3, 4,4, 5};
__constant__ int c_hj[21] = {0,1,2,3,4,5, 1,2,3,4,5, 2,3,4,5, 3,4,5, 4,5, 5};

// ---------------- helpers ----------------
__device__ __forceinline__ void unpack8(uint4 raw, float* p) {
    const __half2* h = (const __half2*)&raw;
#pragma unroll
    for (int j = 0; j < 4; j++) {
        float2 f = __half22float2(h[j]);
        p[2 * j]     = f.x;
        p[2 * j + 1] = f.y;
    }
}

template <int NV>
__device__ __forceinline__ void halfReduce(float* v) {
#pragma unroll
    for (int off = 8; off > 0; off >>= 1)
#pragma unroll
        for (int i = 0; i < NV; i++) v[i] += __shfl_xor_sync(0xffffffffu, v[i], off);
}

__device__ __forceinline__ float selJ0(int k, float fxz, float fxz2, float x, float y, float z) {
    switch (k) {
        case 0: return fxz;
        case 1: return 0.0f;
        case 2: return fxz2;
        case 3: return fxz2 * y;
        case 4: return fxz * z - fxz2 * x;
        default: return -fxz * y;
    }
}
__device__ __forceinline__ float selJ1(int k, float fyz, float fyz2, float x, float y, float z) {
    switch (k) {
        case 0: return 0.0f;
        case 1: return fyz;
        case 2: return fyz2;
        case 3: return -fyz * z + fyz2 * y;
        case 4: return -fyz2 * x;
        default: return fyz * x;
    }
}

__device__ __forceinline__ bool inImage(float px, float py) {
    return (px >= 1.0f) && (px < 511.0f) && (py >= 1.0f) && (py < 511.0f);
}

// bilinear footprint in uint4 (=8 half-channels) units: 16 per pixel
__device__ __forceinline__ void bilin4(float px, float py, int* o, float* w) {
    float x0f = fminf(fmaxf(floorf(px), 0.0f), 511.0f);
    float y0f = fminf(fmaxf(floorf(py), 0.0f), 511.0f);
    float x1f = fminf(x0f + 1.0f, 511.0f);
    float y1f = fminf(y0f + 1.0f, 511.0f);
    float wx = px - x0f, wy = py - y0f;
    int x0 = (int)x0f, x1 = (int)x1f, y0 = (int)y0f, y1 = (int)y1f;
    o[0] = (y0 * WW + x0) * 16;
    o[1] = (y0 * WW + x1) * 16;
    o[2] = (y1 * WW + x0) * 16;
    o[3] = (y1 * WW + x1) * 16;
    w[0] = (1.0f - wx) * (1.0f - wy);
    w[1] = wx * (1.0f - wy);
    w[2] = (1.0f - wx) * wy;
    w[3] = wx * wy;
}

// ---------------- init ----------------
__global__ void k_init(const float* __restrict__ R0, const float* __restrict__ t0) {
    int i = threadIdx.x;
    if (i < 9) { g_R[i] = R0[i]; g_Rn[i] = R0[i]; }
    if (i < 3) { g_t[i] = t0[i]; g_tn[i] = t0[i]; }
    if (i == 0) {
        g_lam = 0.01f; g_costbest = 0.0;
        g_tacc[0] = 0.0; g_tacc[1] = 1.0;
        g_count = 0u;
    }
    if (i < 29) g_acc[i] = 0.0;
}

// ---------------- transpose (C,H,W) f32 -> (H*W, C) f16 ----------------
__global__ void __launch_bounds__(256) k_transpose(const float* __restrict__ fq) {
    __shared__ float sh[64][NC + 1];
    int pix0 = blockIdx.x * 64;
    int tid = threadIdx.x;
    int px = tid & 63;
    int crow = tid >> 6;
#pragma unroll
    for (int cb = 0; cb < NC; cb += 4) {
        int c = cb + crow;
        sh[px][c] = fq[c * NHW + pix0 + px];
    }
    __syncthreads();
    int cpair = tid & 63;
    int prow = tid >> 6;
    __half2* out2 = (__half2*)g_fqH;
#pragma unroll
    for (int pb = 0; pb < 64; pb += 4) {
        int p = pb + prow;
        __half2 h = __floats2half2_rn(sh[p][2 * cpair], sh[p][2 * cpair + 1]);
        out2[(size_t)(pix0 + p) * 64 + cpair] = h;
    }
}

// ---------------- fused fp32 solve (one thread of last-arriving block) ----------------
// Pass `iter` just evaluated H/G/cost at candidate pose g_Rn (= initial pose for iter 0).
// Decide acceptance of g_Rn (iter>0), commit, then build next candidate from saved H/G.
__device__ void do_solve(int iter) {
    volatile double* acc = g_acc;
    double cn = acc[27] / acc[28];
    if (iter == 0) {
        g_costbest = cn;
        const int dix[6] = {0, 6, 11, 15, 18, 20};
#pragma unroll
        for (int i = 0; i < 6; i++) g_jac[i] = 1.0f / (1.0f + sqrtf((float)acc[dix[i]]));
#pragma unroll
        for (int i = 0; i < 27; i++) g_Hsav[i] = acc[i];
        // g_R already equals g_Rn (initial pose)
    } else {
        bool a = (cn <= g_costbest);
        float l = g_lam * (a ? 0.1f : 10.0f);
        g_lam = fminf(fmaxf(l, 1e-8f), 1e4f);
        if (a) {
            g_costbest = cn;
#pragma unroll
            for (int i = 0; i < 9; i++) g_R[i] = g_Rn[i];
#pragma unroll
            for (int i = 0; i < 3; i++) g_t[i] = g_tn[i];
#pragma unroll
            for (int i = 0; i < 27; i++) g_Hsav[i] = acc[i];
        }
    }

    float jac[6];
#pragma unroll
    for (int i = 0; i < 6; i++) jac[i] = g_jac[i];

    float A[6][7];
    {
        int idx = 0;
#pragma unroll
        for (int i = 0; i < 6; i++)
#pragma unroll
            for (int j = i; j < 6; j++) {
                float v = (float)g_Hsav[idx++] * jac[i] * jac[j];
                A[i][j] = v;
                A[j][i] = v;
            }
    }
    float lam = g_lam;
#pragma unroll
    for (int i = 0; i < 6; i++) {
        float d = A[i][i];
        A[i][i] = d + (d + 1e-9f) * lam;
        A[i][6] = -(float)g_Hsav[21 + i] * jac[i];
    }
    for (int col = 0; col < 6; col++) {
        int piv = col;
        float best = fabsf(A[col][col]);
        for (int r = col + 1; r < 6; r++) {
            float v = fabsf(A[r][col]);
            if (v > best) { best = v; piv = r; }
        }
        if (piv != col)
            for (int j = 0; j < 7; j++) { float t = A[col][j]; A[col][j] = A[piv][j]; A[piv][j] = t; }
        float ip = 1.0f / A[col][col];
        for (int r = col + 1; r < 6; r++) {
            float f = A[r][col] * ip;
            for (int j = col; j < 7; j++) A[r][j] -= f * A[col][j];
        }
    }
    float x[6];
#pragma unroll
    for (int i = 5; i >= 0; i--) {
        float v = A[i][6];
#pragma unroll
        for (int j = 0; j < 6; j++)
            if (j > i) v -= A[i][j] * x[j];
        x[i] = v / A[i][i];
    }
    float delta[6];
#pragma unroll
    for (int i = 0; i < 6; i++) delta[i] = x[i] * jac[i];

    float w0 = delta[3], w1 = delta[4], w2 = delta[5];
    float th2 = w0 * w0 + w1 * w1 + w2 * w2;
    float th = sqrtf(th2);
    float Ac, Bc;
    if (th < 1e-7f) { Ac = 1.0f; Bc = 0.5f; }
    else            { Ac = sinf(th) / th; Bc = (1.0f - cosf(th)) / th2; }
    float Wm[9] = {0.0f, -w2, w1, w2, 0.0f, -w0, -w1, w0, 0.0f};
    float W2[9];
#pragma unroll
    for (int i = 0; i < 3; i++)
#pragma unroll
        for (int j = 0; j < 3; j++) {
            float s2 = 0.0f;
#pragma unroll
            for (int k = 0; k < 3; k++) s2 += Wm[i * 3 + k] * Wm[k * 3 + j];
            W2[i * 3 + j] = s2;
        }
    float dr[9];
#pragma unroll
    for (int i = 0; i < 9; i++)
        dr[i] = ((i % 4) == 0 ? 1.0f : 0.0f) + Ac * Wm[i] + Bc * W2[i];

    float Rl[9], Tl[3];
#pragma unroll
    for (int i = 0; i < 9; i++) Rl[i] = g_R[i];
#pragma unroll
    for (int i = 0; i < 3; i++) Tl[i] = g_t[i];
#pragma unroll
    for (int i = 0; i < 3; i++) {
#pragma unroll
        for (int j = 0; j < 3; j++) {
            float s2 = 0.0f;
#pragma unroll
            for (int k = 0; k < 3; k++) s2 += dr[i * 3 + k] * Rl[k * 3 + j];
            g_Rn[i * 3 + j] = s2;
        }
        g_tn[i] = dr[i * 3] * Tl[0] + dr[i * 3 + 1] * Tl[1] + dr[i * 3 + 2] * Tl[2] + delta[i];
    }
#pragma unroll
    for (int i = 0; i < 29; i++) g_acc[i] = 0.0;
    g_count = 0u;
}

// accumulator slot value (0..28) for one point
__device__ __forceinline__ float valForIdx(int idx, float Mxx, float Mxy, float Myy,
                                           float g2x, float g2y, float errsq,
                                           float fxz, float fxz2, float fyz, float fyz2,
                                           float x_, float y_, float d) {
    if (idx < 21) {
        int i = c_hi[idx], j = c_hj[idx];
        float a0 = selJ0(i, fxz, fxz2, x_, y_, d);
        float a1 = selJ1(i, fyz, fyz2, x_, y_, d);
        float b0 = selJ0(j, fxz, fxz2, x_, y_, d);
        float b1 = selJ1(j, fyz, fyz2, x_, y_, d);
        float u  = Mxx * a0 + Mxy * a1;
        float vv = Mxy * a0 + Myy * a1;
        return u * b0 + vv * b1;
    } else if (idx < 27) {
        int j = idx - 21;
        float b0 = selJ0(j, fxz, fxz2, x_, y_, d);
        float b1 = selJ1(j, fyz, fyz2, x_, y_, d);
        return g2x * b0 + g2y * b1;
    } else if (idx == 27) {
        return errsq;
    }
    return 1.0f;
}

// ---------------- main LM accumulation at candidate pose (+ fused solve) ----------------
__global__ void __launch_bounds__(256) k_main(const float* __restrict__ p3D,
                                              const float* __restrict__ fref,
                                              const float* __restrict__ Km,
                                              int N, int iter) {
    int tid = threadIdx.x, lane = tid & 31, warp = tid >> 5;
    int hl = lane & 15;
    int side = lane >> 4;
    int wid = blockIdx.x * 8 + warp;
    int pt = 2 * wid + side;
    bool vp = (pt < N);
    int ptc = vp ? pt : 0;

    float R[9], T[3];
#pragma unroll
    for (int i = 0; i < 9; i++) R[i] = g_Rn[i];
#pragma unroll
    for (int i = 0; i < 3; i++) T[i] = g_tn[i];
    float fx = Km[0], fy = Km[4], cx = Km[2], cy = Km[5];

    float Px = p3D[3 * ptc], Py = p3D[3 * ptc + 1], Pz = p3D[3 * ptc + 2];
    float x_ = R[0] * Px + R[1] * Py + R[2] * Pz + T[0];
    float y_ = R[3] * Px + R[4] * Py + R[5] * Pz + T[1];
    float d  = R[6] * Px + R[7] * Py + R[8] * Pz + T[2];
    float izd0 = 1.0f / d;
    float px = x_ * izd0 * fx + cx;
    float py = y_ * izd0 * fy + cy;
    if (iter == 0 && hl == 0 && vp) { g_p2init[2 * pt] = px; g_p2init[2 * pt + 1] = py; }
    bool valid = vp && inImage(px, py);
    if (!valid) { px = 256.0f; py = 256.0f; d = 1.0f; }
    float izd = 1.0f / d;

    float x0f = floorf(px), y0f = floorf(py);
    float wx = px - x0f, wy = py - y0f;
    int x0 = (int)x0f, x1 = x0 + 1, y0 = (int)y0f, y1 = y0 + 1;
    int colo[4] = {(x0 - 1) * 16, x0 * 16, x1 * 16, (x1 < 511 ? x1 + 1 : 511) * 16};
    int rowo[4] = {(y0 - 1) * (WW * 16), y0 * (WW * 16), y1 * (WW * 16),
                   (y1 < 511 ? y1 + 1 : 511) * (WW * 16)};
    float w00 = (1.0f - wx) * (1.0f - wy), w01 = wx * (1.0f - wy);
    float w10 = (1.0f - wx) * wy,          w11 = wx * wy;

    float wgx[16], wgy[16];
#pragma unroll
    for (int k = 0; k < 16; k++) { wgx[k] = 0.0f; wgy[k] = 0.0f; }
    {
        const float KX[3][3] = {{-0.125f, 0.0f, 0.125f}, {-0.25f, 0.0f, 0.25f}, {-0.125f, 0.0f, 0.125f}};
        const float KY[3][3] = {{-0.125f, -0.25f, -0.125f}, {0.0f, 0.0f, 0.0f}, {0.125f, 0.25f, 0.125f}};
        float wb[2][2] = {{w00, w01}, {w10, w11}};
#pragma unroll
        for (int a = 0; a < 2; a++)
#pragma unroll
            for (int b = 0; b < 2; b++) {
                float wc = wb[a][b];
#pragma unroll
                for (int u = 0; u < 3; u++)
#pragma unroll
                    for (int v = 0; v < 3; v++) {
                        wgx[(a + u) * 4 + (b + v)] += wc * KX[u][v];
                        wgy[(a + u) * 4 + (b + v)] += wc * KY[u][v];
                    }
            }
    }

    const uint4* __restrict__ B = (const uint4*)g_fqH;
    float f8[8], gx8[8], gy8[8];
#pragma unroll
    for (int j = 0; j < 8; j++) { f8[j] = 0.0f; gx8[j] = 0.0f; gy8[j] = 0.0f; }
#pragma unroll
    for (int k = 0; k < 16; k++) {
        uint4 raw = __ldg(&B[rowo[k >> 2] + colo[k & 3] + hl]);
        float p[8];
        unpack8(raw, p);
        float ax = wgx[k], ay = wgy[k];
#pragma unroll
        for (int j = 0; j < 8; j++) { gx8[j] += ax * p[j]; gy8[j] += ay * p[j]; }
        if (k == 5 || k == 6 || k == 9 || k == 10) {
            float wf = (k == 5) ? w00 : (k == 6) ? w01 : (k == 9) ? w10 : w11;
#pragma unroll
            for (int j = 0; j < 8; j++) f8[j] += wf * p[j];
        }
    }
    float r8[8];
    {
        const float4* __restrict__ F4p = (const float4*)fref;
        float4 ra = __ldg(&F4p[ptc * 32 + 2 * hl]);
        float4 rb = __ldg(&F4p[ptc * 32 + 2 * hl + 1]);
        r8[0] = ra.x; r8[1] = ra.y; r8[2] = ra.z; r8[3] = ra.w;
        r8[4] = rb.x; r8[5] = rb.y; r8[6] = rb.z; r8[7] = rb.w;
    }

    float s[10];
#pragma unroll
    for (int i = 0; i < 10; i++) s[i] = 0.0f;
#pragma unroll
    for (int j = 0; j < 8; j++) {
        s[0] += f8[j] * f8[j];   s[1] += f8[j] * gx8[j];  s[2] += f8[j] * gy8[j];
        s[3] += gx8[j] * gx8[j]; s[4] += gx8[j] * gy8[j]; s[5] += gy8[j] * gy8[j];
        s[6] += gx8[j] * r8[j];  s[7] += gy8[j] * r8[j];  s[8] += f8[j] * r8[j];
        s[9] += r8[j] * r8[j];
    }
    halfReduce<10>(s);

    float norm  = fmaxf(sqrtf(s[0]), 1e-12f);
    float rnorm = fmaxf(sqrtf(s[9]), 1e-12f);
    float inorm = 1.0f / norm, irn = 1.0f / rnorm;
    float projx = s[1] * inorm, projy = s[2] * inorm;
    float nf2 = s[0] * inorm * inorm;
    float sc  = s[8] * inorm * irn;
    float in2 = inorm * inorm;
    float fac = 2.0f - nf2;
    float Mxx = (s[3] - projx * projx * fac) * in2;
    float Mxy = (s[4] - projx * projy * fac) * in2;
    float Myy = (s[5] - projy * projy * fac) * in2;
    float coef = 1.0f - nf2 + sc;
    float g2x = (projx * coef - s[6] * irn) * inorm;
    float g2y = (projy * coef - s[7] * irn) * inorm;
    float errsq = nf2 - 2.0f * sc + s[9] * irn * irn;

    float fxz = fx * izd, fxz2 = -fx * x_ * izd * izd;
    float fyz = fy * izd, fyz2 = -fy * y_ * izd * izd;
    float vf = valid ? 1.0f : 0.0f;

    double a0 = (double)(vf * valForIdx(hl, Mxx, Mxy, Myy, g2x, g2y, errsq,
                                        fxz, fxz2, fyz, fyz2, x_, y_, d));
    double a1 = 0.0;
    if (hl < 13)
        a1 = (double)(vf * valForIdx(hl + 16, Mxx, Mxy, Myy, g2x, g2y, errsq,
                                     fxz, fxz2, fyz, fyz2, x_, y_, d));
    a0 += __shfl_down_sync(0xffffffffu, a0, 16);
    a1 += __shfl_down_sync(0xffffffffu, a1, 16);

    __shared__ double sred[8][29];
    __shared__ bool s_last;
    if (lane < 16) sred[warp][lane] = a0;
    if (lane < 13) sred[warp][16 + lane] = a1;
    __syncthreads();
    if (warp == 0 && lane < 29) {
        double t2 = 0.0;
#pragma unroll
        for (int w2i = 0; w2i < 8; w2i++) t2 += sred[w2i][lane];
        atomicAdd(&g_acc[lane], t2);
    }
    __syncthreads();
    if (tid == 0) {
        __threadfence();
        unsigned int t = atomicAdd(&g_count, 1u);
        s_last = (t == gridDim.x - 1);
    }
    __syncthreads();
    if (s_last && tid == 0) {
        __threadfence();
        do_solve(iter);
    }
}

// ---------------- trial cost of final candidate c8 ----------------
__global__ void __launch_bounds__(256) k_trial(const float* __restrict__ p3D,
                                               const float* __restrict__ fref,
                                               const float* __restrict__ Km, int N) {
    int tid = threadIdx.x, lane = tid & 31, warp = tid >> 5;
    int hl = lane & 15, side = lane >> 4;
    int wid = blockIdx.x * 8 + warp;
    int pt = 2 * wid + side;
    bool vp = (pt < N);
    int ptc = vp ? pt : 0;

    float R[9], T[3];
#pragma unroll
    for (int i = 0; i < 9; i++) R[i] = g_Rn[i];
#pragma unroll
    for (int i = 0; i < 3; i++) T[i] = g_tn[i];
    float fx = Km[0], fy = Km[4], cx = Km[2], cy = Km[5];

    float Px = p3D[3 * ptc], Py = p3D[3 * ptc + 1], Pz = p3D[3 * ptc + 2];
    float x_ = R[0] * Px + R[1] * Py + R[2] * Pz + T[0];
    float y_ = R[3] * Px + R[4] * Py + R[5] * Pz + T[1];
    float d  = R[6] * Px + R[7] * Py + R[8] * Pz + T[2];
    float izd = 1.0f / d;
    float px = x_ * izd * fx + cx;
    float py = y_ * izd * fy + cy;
    bool valid = vp && inImage(px, py);
    if (!valid) { px = 256.0f; py = 256.0f; }

    int o[4]; float w[4];
    bilin4(px, py, o, w);
    const uint4* __restrict__ B = (const uint4*)g_fqH;
    float f8[8];
#pragma unroll
    for (int j = 0; j < 8; j++) f8[j] = 0.0f;
#pragma unroll
    for (int k = 0; k < 4; k++) {
        uint4 raw = __ldg(&B[o[k] + hl]);
        float p[8];
        unpack8(raw, p);
#pragma unroll
        for (int j = 0; j < 8; j++) f8[j] += w[k] * p[j];
    }
    float r8[8];
    {
        const float4* __restrict__ F4p = (const float4*)fref;
        float4 ra = __ldg(&F4p[ptc * 32 + 2 * hl]);
        float4 rb = __ldg(&F4p[ptc * 32 + 2 * hl + 1]);
        r8[0] = ra.x; r8[1] = ra.y; r8[2] = ra.z; r8[3] = ra.w;
        r8[4] = rb.x; r8[5] = rb.y; r8[6] = rb.z; r8[7] = rb.w;
    }
    float s[3] = {0.0f, 0.0f, 0.0f};
#pragma unroll
    for (int j = 0; j < 8; j++) {
        s[0] += f8[j] * f8[j];
        s[1] += f8[j] * r8[j];
        s[2] += r8[j] * r8[j];
    }
    halfReduce<3>(s);

    float inorm = 1.0f / fmaxf(sqrtf(s[0]), 1e-12f);
    float irn   = 1.0f / fmaxf(sqrtf(s[2]), 1e-12f);
    float errsq = s[0] * inorm * inorm - 2.0f * s[1] * inorm * irn + s[2] * irn * irn;
    float vf = valid ? 1.0f : 0.0f;

    double eD = (hl == 0) ? (double)(errsq * vf) : 0.0;
    double eC = (hl == 0) ? (double)vf : 0.0;
    eD += __shfl_down_sync(0xffffffffu, eD, 16);
    eC += __shfl_down_sync(0xffffffffu, eC, 16);

    __shared__ double sD[8], sC[8];
    if (lane == 0) { sD[warp] = eD; sC[warp] = eC; }
    __syncthreads();
    if (tid == 0) {
        double a = 0.0, b = 0.0;
#pragma unroll
        for (int i = 0; i < 8; i++) { a += sD[i]; b += sC[i]; }
        atomicAdd(&g_tacc[0], a);
        atomicAdd(&g_tacc[1], b);
    }
}

// ---------------- final costs + output ----------------
__global__ void __launch_bounds__(256) k_final(const float* __restrict__ p3D,
                                               const float* __restrict__ fref,
                                               const float* __restrict__ Km,
                                               int N, float* __restrict__ out) {
    int tid = threadIdx.x, lane = tid & 31, warp = tid >> 5;
    int hl = lane & 15, side = lane >> 4;
    int wid = blockIdx.x * 8 + warp;
    int pt = 2 * wid + side;
    bool vp = (pt < N);
    int ptc = vp ? pt : 0;

    // decide acceptance of c8 (init seeded tacc[1]=1 so this is safe pre-trial;
    // here tacc holds the real c8 trial sums)
    double cn = g_tacc[0] / g_tacc[1];
    bool accPrev = (cn <= g_costbest);
    float R[9], T[3];
#pragma unroll
    for (int i = 0; i < 9; i++) R[i] = accPrev ? g_Rn[i] : g_R[i];
#pragma unroll
    for (int i = 0; i < 3; i++) T[i] = accPrev ? g_tn[i] : g_t[i];
    float fx = Km[0], fy = Km[4], cx = Km[2], cy = Km[5];

    if (blockIdx.x == 0 && tid == 0) {
#pragma unroll
        for (int i = 0; i < 9; i++) out[i] = R[i];
#pragma unroll
        for (int i = 0; i < 3; i++) out[9 + i] = T[i];
    }
    const float NANF = __int_as_float(0x7fc00000);

    float pix = g_p2init[2 * ptc], piy = g_p2init[2 * ptc + 1];
    float Px = p3D[3 * ptc], Py = p3D[3 * ptc + 1], Pz = p3D[3 * ptc + 2];
    float x_ = R[0] * Px + R[1] * Py + R[2] * Pz + T[0];
    float y_ = R[3] * Px + R[4] * Py + R[5] * Pz + T[1];
    float d  = R[6] * Px + R[7] * Py + R[8] * Pz + T[2];
    float izd = 1.0f / d;
    float pfx = x_ * izd * fx + cx;
    float pfy = y_ * izd * fy + cy;

    bool vi = inImage(pix, piy);
    bool vfv = inImage(pfx, pfy);
    float pixc = vi ? pix : 256.0f, piyc = vi ? piy : 256.0f;
    float pfxc = vfv ? pfx : 256.0f, pfyc = vfv ? pfy : 256.0f;

    int oi[4], of_[4];
    float wi[4], wf[4];
    bilin4(pixc, piyc, oi, wi);
    bilin4(pfxc, pfyc, of_, wf);

    const uint4* __restrict__ B = (const uint4*)g_fqH;
    float fi8[8], ff8[8];
#pragma unroll
    for (int j = 0; j < 8; j++) { fi8[j] = 0.0f; ff8[j] = 0.0f; }
#pragma unroll
    for (int k = 0; k < 4; k++) {
        uint4 rawi = __ldg(&B[oi[k] + hl]);
        uint4 rawf = __ldg(&B[of_[k] + hl]);
        float pi[8], pf[8];
        unpack8(rawi, pi);
        unpack8(rawf, pf);
#pragma unroll
        for (int j = 0; j < 8; j++) {
            fi8[j] += wi[k] * pi[j];
            ff8[j] += wf[k] * pf[j];
        }
    }
    float r8[8];
    {
        const float4* __restrict__ F4p = (const float4*)fref;
        float4 ra = __ldg(&F4p[ptc * 32 + 2 * hl]);
        float4 rb = __ldg(&F4p[ptc * 32 + 2 * hl + 1]);
        r8[0] = ra.x; r8[1] = ra.y; r8[2] = ra.z; r8[3] = ra.w;
        r8[4] = rb.x; r8[5] = rb.y; r8[6] = rb.z; r8[7] = rb.w;
    }
    float s[5] = {0, 0, 0, 0, 0};
#pragma unroll
    for (int j = 0; j < 8; j++) {
        s[0] += fi8[j] * fi8[j];
        s[1] += fi8[j] * r8[j];
        s[2] += ff8[j] * ff8[j];
        s[3] += ff8[j] * r8[j];
        s[4] += r8[j] * r8[j];
    }
    halfReduce<5>(s);

    if (hl == 0 && vp) {
        float irn = 1.0f / fmaxf(sqrtf(s[4]), 1e-12f);
        float ini = 1.0f / fmaxf(sqrtf(s[0]), 1e-12f);
        float inf_ = 1.0f / fmaxf(sqrtf(s[2]), 1e-12f);
        float rr = s[4] * irn * irn;
        float ci = rr - 2.0f * s[1] * ini * irn + s[0] * ini * ini;
        float cf = rr - 2.0f * s[3] * inf_ * irn + s[2] * inf_ * inf_;
        out[12 + pt]     = vi  ? ci : NANF;
        out[12 + N + pt] = vfv ? cf : NANF;
    }
}

// ---------------- launch ----------------
extern "C" void kernel_launch(void* const* d_in, const int* in_sizes, int n_in,
                              void* d_out, int out_size) {
    const float* p3D  = (const float*)d_in[0];
    const float* fref = (const float*)d_in[1];
    const float* fq   = (const float*)d_in[2];
    const float* Km   = (const float*)d_in[3];
    const float* R0   = (const float*)d_in[4];
    const float* t0   = (const float*)d_in[5];
    float* out = (float*)d_out;
    int N = in_sizes[0] / 3;
    if (N > MAXN) N = MAXN;

    int grid = (N + 15) / 16;   // 8 warps/block * 2 pts/warp
    k_init<<<1, 32>>>(R0, t0);
    k_transpose<<<NHW / 64, 256>>>(fq);
    for (int i = 0; i < 8; i++)
        k_main<<<grid, 256>>>(p3D, fref, Km, N, i);   // evaluates candidate c_i (c_0 = init)
    k_trial<<<grid, 256>>>(p3D, fref, Km, N);         // cost of c8 only
    k_final<<<grid, 256>>>(p3D, fref, Km, N, out);
}

// round 9
// speedup vs baseline: 1.5981x; 1.0333x over previous
#include <cuda_runtime.h>
#include <cuda_fp16.h>
#include <math.h>

#define NC   128
#define WW   512
#define HH   512
#define NHW  (HH*WW)
#define MAXN 10000

// ---------------- persistent device state ----------------
__device__ __align__(16) __half g_fqH[NC * NHW];  // (pixel, channel) layout, fp16
__device__ float  g_p2init[2 * MAXN];
__device__ double g_acc[29];    // [0..20] Hess uptri, [21..26] Grad, [27] cost, [28] count
__device__ double g_Hsav[27];   // H/G snapshot at last accepted pose
__device__ double g_tacc[2];    // final trial cost sum, count
__device__ double g_costbest;
__device__ float  g_R[9], g_t[3];     // accepted pose
__device__ float  g_Rn[9], g_tn[3];   // eval / candidate pose
__device__ float  g_lam, g_jac[6];
__device__ unsigned int g_count;

__constant__ int c_hi[21] = {0,0,0,0,0,0, 1,1,1,1,1, 2,2,2,2, 3,3,3, 4,4, 5};
__constant__ int c_hj[21] = {0,1,2,3,4,5, 1,2,3,4,5, 2,3,4,5, 3,4,5, 4,5, 5};

// ---------------- helpers ----------------
__device__ __forceinline__ void unpack8(uint4 raw, float* p) {
    const __half2* h = (const __half2*)&raw;
#pragma unroll
    for (int j = 0; j < 4; j++) {
        float2 f = __half22float2(h[j]);
        p[2 * j]     = f.x;
        p[2 * j + 1] = f.y;
    }
}

template <int NV>
__device__ __forceinline__ void halfReduce(float* v) {
#pragma unroll
    for (int off = 8; off > 0; off >>= 1)
#pragma unroll
        for (int i = 0; i < NV; i++) v[i] += __shfl_xor_sync(0xffffffffu, v[i], off);
}

__device__ __forceinline__ float selJ0(int k, float fxz, float fxz2, float x, float y, float z) {
    switch (k) {
        case 0: return fxz;
        case 1: return 0.0f;
        case 2: return fxz2;
        case 3: return fxz2 * y;
        case 4: return fxz * z - fxz2 * x;
        default: return -fxz * y;
    }
}
__device__ __forceinline__ float selJ1(int k, float fyz, float fyz2, float x, float y, float z) {
    switch (k) {
        case 0: return 0.0f;
        case 1: return fyz;
        case 2: return fyz2;
        case 3: return -fyz * z + fyz2 * y;
        case 4: return -fyz2 * x;
        default: return fyz * x;
    }
}

__device__ __forceinline__ bool inImage(float px, float py) {
    return (px >= 1.0f) && (px < 511.0f) && (py >= 1.0f) && (py < 511.0f);
}

// bilinear footprint in uint4 (=8 half-channels) units: 16 per pixel
__device__ __forceinline__ void bilin4(float px, float py, int* o, float* w) {
    float x0f = fminf(fmaxf(floorf(px), 0.0f), 511.0f);
    float y0f = fminf(fmaxf(floorf(py), 0.0f), 511.0f);
    float x1f = fminf(x0f + 1.0f, 511.0f);
    float y1f = fminf(y0f + 1.0f, 511.0f);
    float wx = px - x0f, wy = py - y0f;
    int x0 = (int)x0f, x1 = (int)x1f, y0 = (int)y0f, y1 = (int)y1f;
    o[0] = (y0 * WW + x0) * 16;
    o[1] = (y0 * WW + x1) * 16;
    o[2] = (y1 * WW + x0) * 16;
    o[3] = (y1 * WW + x1) * 16;
    w[0] = (1.0f - wx) * (1.0f - wy);
    w[1] = wx * (1.0f - wy);
    w[2] = (1.0f - wx) * wy;
    w[3] = wx * wy;
}

// ---------------- init ----------------
__global__ void k_init(const float* __restrict__ R0, const float* __restrict__ t0) {
    int i = threadIdx.x;
    if (i < 9) { g_R[i] = R0[i]; g_Rn[i] = R0[i]; }
    if (i < 3) { g_t[i] = t0[i]; g_tn[i] = t0[i]; }
    if (i == 0) {
        g_lam = 0.01f; g_costbest = 0.0;
        g_tacc[0] = 0.0; g_tacc[1] = 1.0;
        g_count = 0u;
    }
    if (i < 29) g_acc[i] = 0.0;
}

// ---------------- transpose (C,H,W) f32 -> (H*W, C) f16 ----------------
__global__ void __launch_bounds__(256) k_transpose(const float* __restrict__ fq) {
    __shared__ float sh[64][NC + 1];
    int pix0 = blockIdx.x * 64;
    int tid = threadIdx.x;
    int px = tid & 63;
    int crow = tid >> 6;
#pragma unroll
    for (int cb = 0; cb < NC; cb += 4) {
        int c = cb + crow;
        sh[px][c] = fq[c * NHW + pix0 + px];
    }
    __syncthreads();
    int cpair = tid & 63;
    int prow = tid >> 6;
    __half2* out2 = (__half2*)g_fqH;
#pragma unroll
    for (int pb = 0; pb < 64; pb += 4) {
        int p = pb + prow;
        __half2 h = __floats2half2_rn(sh[p][2 * cpair], sh[p][2 * cpair + 1]);
        out2[(size_t)(pix0 + p) * 64 + cpair] = h;
    }
}

// ---------------- fused fp32 solve (one thread of last-arriving block) ----------------
__device__ void do_solve(int iter) {
    volatile double* acc = g_acc;
    double cn = acc[27] / acc[28];
    if (iter == 0) {
        g_costbest = cn;
        const int dix[6] = {0, 6, 11, 15, 18, 20};
#pragma unroll
        for (int i = 0; i < 6; i++) g_jac[i] = 1.0f / (1.0f + sqrtf((float)acc[dix[i]]));
#pragma unroll
        for (int i = 0; i < 27; i++) g_Hsav[i] = acc[i];
    } else {
        bool a = (cn <= g_costbest);
        float l = g_lam * (a ? 0.1f : 10.0f);
        g_lam = fminf(fmaxf(l, 1e-8f), 1e4f);
        if (a) {
            g_costbest = cn;
#pragma unroll
            for (int i = 0; i < 9; i++) g_R[i] = g_Rn[i];
#pragma unroll
            for (int i = 0; i < 3; i++) g_t[i] = g_tn[i];
#pragma unroll
            for (int i = 0; i < 27; i++) g_Hsav[i] = acc[i];
        }
    }

    float jac[6];
#pragma unroll
    for (int i = 0; i < 6; i++) jac[i] = g_jac[i];

    float A[6][7];
    {
        int idx = 0;
#pragma unroll
        for (int i = 0; i < 6; i++)
#pragma unroll
            for (int j = i; j < 6; j++) {
                float v = (float)g_Hsav[idx++] * jac[i] * jac[j];
                A[i][j] = v;
                A[j][i] = v;
            }
    }
    float lam = g_lam;
#pragma unroll
    for (int i = 0; i < 6; i++) {
        float d = A[i][i];
        A[i][i] = d + (d + 1e-9f) * lam;
        A[i][6] = -(float)g_Hsav[21 + i] * jac[i];
    }
    for (int col = 0; col < 6; col++) {
        int piv = col;
        float best = fabsf(A[col][col]);
        for (int r = col + 1; r < 6; r++) {
            float v = fabsf(A[r][col]);
            if (v > best) { best = v; piv = r; }
        }
        if (piv != col)
            for (int j = 0; j < 7; j++) { float t = A[col][j]; A[col][j] = A[piv][j]; A[piv][j] = t; }
        float ip = 1.0f / A[col][col];
        for (int r = col + 1; r < 6; r++) {
            float f = A[r][col] * ip;
            for (int j = col; j < 7; j++) A[r][j] -= f * A[col][j];
        }
    }
    float x[6];
#pragma unroll
    for (int i = 5; i >= 0; i--) {
        float v = A[i][6];
#pragma unroll
        for (int j = 0; j < 6; j++)
            if (j > i) v -= A[i][j] * x[j];
        x[i] = v / A[i][i];
    }
    float delta[6];
#pragma unroll
    for (int i = 0; i < 6; i++) delta[i] = x[i] * jac[i];

    float w0 = delta[3], w1 = delta[4], w2 = delta[5];
    float th2 = w0 * w0 + w1 * w1 + w2 * w2;
    float th = sqrtf(th2);
    float Ac, Bc;
    if (th < 1e-7f) { Ac = 1.0f; Bc = 0.5f; }
    else            { Ac = sinf(th) / th; Bc = (1.0f - cosf(th)) / th2; }
    float Wm[9] = {0.0f, -w2, w1, w2, 0.0f, -w0, -w1, w0, 0.0f};
    float W2[9];
#pragma unroll
    for (int i = 0; i < 3; i++)
#pragma unroll
        for (int j = 0; j < 3; j++) {
            float s2 = 0.0f;
#pragma unroll
            for (int k = 0; k < 3; k++) s2 += Wm[i * 3 + k] * Wm[k * 3 + j];
            W2[i * 3 + j] = s2;
        }
    float dr[9];
#pragma unroll
    for (int i = 0; i < 9; i++)
        dr[i] = ((i % 4) == 0 ? 1.0f : 0.0f) + Ac * Wm[i] + Bc * W2[i];

    float Rl[9], Tl[3];
#pragma unroll
    for (int i = 0; i < 9; i++) Rl[i] = g_R[i];
#pragma unroll
    for (int i = 0; i < 3; i++) Tl[i] = g_t[i];
#pragma unroll
    for (int i = 0; i < 3; i++) {
#pragma unroll
        for (int j = 0; j < 3; j++) {
            float s2 = 0.0f;
#pragma unroll
            for (int k = 0; k < 3; k++) s2 += dr[i * 3 + k] * Rl[k * 3 + j];
            g_Rn[i * 3 + j] = s2;
        }
        g_tn[i] = dr[i * 3] * Tl[0] + dr[i * 3 + 1] * Tl[1] + dr[i * 3 + 2] * Tl[2] + delta[i];
    }
#pragma unroll
    for (int i = 0; i < 29; i++) g_acc[i] = 0.0;
    g_count = 0u;
}

// accumulator slot value (0..28) for one point
__device__ __forceinline__ float valForIdx(int idx, float Mxx, float Mxy, float Myy,
                                           float g2x, float g2y, float errsq,
                                           float fxz, float fxz2, float fyz, float fyz2,
                                           float x_, float y_, float d) {
    if (idx < 21) {
        int i = c_hi[idx], j = c_hj[idx];
        float a0 = selJ0(i, fxz, fxz2, x_, y_, d);
        float a1 = selJ1(i, fyz, fyz2, x_, y_, d);
        float b0 = selJ0(j, fxz, fxz2, x_, y_, d);
        float b1 = selJ1(j, fyz, fyz2, x_, y_, d);
        float u  = Mxx * a0 + Mxy * a1;
        float vv = Mxy * a0 + Myy * a1;
        return u * b0 + vv * b1;
    } else if (idx < 27) {
        int j = idx - 21;
        float b0 = selJ0(j, fxz, fxz2, x_, y_, d);
        float b1 = selJ1(j, fyz, fyz2, x_, y_, d);
        return g2x * b0 + g2y * b1;
    } else if (idx == 27) {
        return errsq;
    }
    return 1.0f;
}

// ---------------- main LM accumulation at candidate pose (+ fused solve) ----------------
__global__ void __launch_bounds__(256, 3) k_main(const float* __restrict__ p3D,
                                                 const float* __restrict__ fref,
                                                 const float* __restrict__ Km,
                                                 int N, int iter) {
    int tid = threadIdx.x, lane = tid & 31, warp = tid >> 5;
    int hl = lane & 15;
    int side = lane >> 4;
    int wid = blockIdx.x * 8 + warp;
    int pt = 2 * wid + side;
    bool vp = (pt < N);
    int ptc = vp ? pt : 0;

    float R[9], T[3];
#pragma unroll
    for (int i = 0; i < 9; i++) R[i] = g_Rn[i];
#pragma unroll
    for (int i = 0; i < 3; i++) T[i] = g_tn[i];
    float fx = Km[0], fy = Km[4], cx = Km[2], cy = Km[5];

    float Px = p3D[3 * ptc], Py = p3D[3 * ptc + 1], Pz = p3D[3 * ptc + 2];
    float x_ = R[0] * Px + R[1] * Py + R[2] * Pz + T[0];
    float y_ = R[3] * Px + R[4] * Py + R[5] * Pz + T[1];
    float d  = R[6] * Px + R[7] * Py + R[8] * Pz + T[2];
    float izd0 = 1.0f / d;
    float px = x_ * izd0 * fx + cx;
    float py = y_ * izd0 * fy + cy;
    if (iter == 0 && hl == 0 && vp) { g_p2init[2 * pt] = px; g_p2init[2 * pt + 1] = py; }
    bool valid = vp && inImage(px, py);
    if (!valid) { px = 256.0f; py = 256.0f; d = 1.0f; }
    float izd = 1.0f / d;

    float x0f = floorf(px), y0f = floorf(py);
    float wx = px - x0f, wy = py - y0f;
    int x0 = (int)x0f, x1 = x0 + 1, y0 = (int)y0f, y1 = y0 + 1;
    int colo[4] = {(x0 - 1) * 16, x0 * 16, x1 * 16, (x1 < 511 ? x1 + 1 : 511) * 16};
    int rowo[4] = {(y0 - 1) * (WW * 16), y0 * (WW * 16), y1 * (WW * 16),
                   (y1 < 511 ? y1 + 1 : 511) * (WW * 16)};

    // separable sobel x bilinear weights: wgx=Ay8[i]Bx[j], wgy=By8[i]Ax[j]
    float Ax[4]  = {1.0f - wx, 2.0f - wx, 1.0f + wx, wx};
    float Bx[4]  = {-(1.0f - wx), -wx, 1.0f - wx, wx};
    float Ay8[4] = {(1.0f - wy) * 0.125f, (2.0f - wy) * 0.125f,
                    (1.0f + wy) * 0.125f, wy * 0.125f};
    float By8[4] = {-(1.0f - wy) * 0.125f, -wy * 0.125f,
                    (1.0f - wy) * 0.125f, wy * 0.125f};
    float fxw0 = 1.0f - wx, fyw0 = 1.0f - wy;

    const uint4* __restrict__ B = (const uint4*)g_fqH;
    float f8[8], gx8[8], gy8[8];
#pragma unroll
    for (int j = 0; j < 8; j++) { f8[j] = 0.0f; gx8[j] = 0.0f; gy8[j] = 0.0f; }
#pragma unroll
    for (int i = 0; i < 4; i++) {
        float rx[8], ra[8];
#pragma unroll
        for (int j = 0; j < 8; j++) { rx[j] = 0.0f; ra[j] = 0.0f; }
#pragma unroll
        for (int j = 0; j < 4; j++) {
            uint4 raw = __ldg(&B[rowo[i] + colo[j] + hl]);
            float p[8];
            unpack8(raw, p);
#pragma unroll
            for (int c = 0; c < 8; c++) {
                rx[c] += Bx[j] * p[c];
                ra[c] += Ax[j] * p[c];
            }
            if ((i == 1 || i == 2) && (j == 1 || j == 2)) {
                float wcf = ((j == 1) ? fxw0 : wx) * ((i == 1) ? fyw0 : wy);
#pragma unroll
                for (int c = 0; c < 8; c++) f8[c] += wcf * p[c];
            }
        }
#pragma unroll
        for (int c = 0; c < 8; c++) {
            gx8[c] += Ay8[i] * rx[c];
            gy8[c] += By8[i] * ra[c];
        }
    }
    float r8[8];
    {
        const float4* __restrict__ F4p = (const float4*)fref;
        float4 ra4 = __ldg(&F4p[ptc * 32 + 2 * hl]);
        float4 rb4 = __ldg(&F4p[ptc * 32 + 2 * hl + 1]);
        r8[0] = ra4.x; r8[1] = ra4.y; r8[2] = ra4.z; r8[3] = ra4.w;
        r8[4] = rb4.x; r8[5] = rb4.y; r8[6] = rb4.z; r8[7] = rb4.w;
    }

    float s[10];
#pragma unroll
    for (int i = 0; i < 10; i++) s[i] = 0.0f;
#pragma unroll
    for (int j = 0; j < 8; j++) {
        s[0] += f8[j] * f8[j];   s[1] += f8[j] * gx8[j];  s[2] += f8[j] * gy8[j];
        s[3] += gx8[j] * gx8[j]; s[4] += gx8[j] * gy8[j]; s[5] += gy8[j] * gy8[j];
        s[6] += gx8[j] * r8[j];  s[7] += gy8[j] * r8[j];  s[8] += f8[j] * r8[j];
        s[9] += r8[j] * r8[j];
    }
    halfReduce<10>(s);

    float norm  = fmaxf(sqrtf(s[0]), 1e-12f);
    float rnorm = fmaxf(sqrtf(s[9]), 1e-12f);
    float inorm = 1.0f / norm, irn = 1.0f / rnorm;
    float projx = s[1] * inorm, projy = s[2] * inorm;
    float nf2 = s[0] * inorm * inorm;
    float sc  = s[8] * inorm * irn;
    float in2 = inorm * inorm;
    float fac = 2.0f - nf2;
    float Mxx = (s[3] - projx * projx * fac) * in2;
    float Mxy = (s[4] - projx * projy * fac) * in2;
    float Myy = (s[5] - projy * projy * fac) * in2;
    float coef = 1.0f - nf2 + sc;
    float g2x = (projx * coef - s[6] * irn) * inorm;
    float g2y = (projy * coef - s[7] * irn) * inorm;
    float errsq = nf2 - 2.0f * sc + s[9] * irn * irn;

    float fxz = fx * izd, fxz2 = -fx * x_ * izd * izd;
    float fyz = fy * izd, fyz2 = -fy * y_ * izd * izd;
    float vf = valid ? 1.0f : 0.0f;

    double a0 = (double)(vf * valForIdx(hl, Mxx, Mxy, Myy, g2x, g2y, errsq,
                                        fxz, fxz2, fyz, fyz2, x_, y_, d));
    double a1 = 0.0;
    if (hl < 13)
        a1 = (double)(vf * valForIdx(hl + 16, Mxx, Mxy, Myy, g2x, g2y, errsq,
                                     fxz, fxz2, fyz, fyz2, x_, y_, d));
    a0 += __shfl_down_sync(0xffffffffu, a0, 16);
    a1 += __shfl_down_sync(0xffffffffu, a1, 16);

    __shared__ double sred[8][29];
    __shared__ bool s_last;
    if (lane < 16) sred[warp][lane] = a0;
    if (lane < 13) sred[warp][16 + lane] = a1;
    __syncthreads();
    if (warp == 0 && lane < 29) {
        double t2 = 0.0;
#pragma unroll
        for (int w2i = 0; w2i < 8; w2i++) t2 += sred[w2i][lane];
        atomicAdd(&g_acc[lane], t2);
    }
    __syncthreads();
    if (tid == 0) {
        __threadfence();
        unsigned int t = atomicAdd(&g_count, 1u);
        s_last = (t == gridDim.x - 1);
    }
    __syncthreads();
    if (s_last && tid == 0) {
        __threadfence();
        do_solve(iter);
    }
}

// ---------------- trial cost of final candidate c8 ----------------
__global__ void __launch_bounds__(256) k_trial(const float* __restrict__ p3D,
                                               const float* __restrict__ fref,
                                               const float* __restrict__ Km, int N) {
    int tid = threadIdx.x, lane = tid & 31, warp = tid >> 5;
    int hl = lane & 15, side = lane >> 4;
    int wid = blockIdx.x * 8 + warp;
    int pt = 2 * wid + side;
    bool vp = (pt < N);
    int ptc = vp ? pt : 0;

    float R[9], T[3];
#pragma unroll
    for (int i = 0; i < 9; i++) R[i] = g_Rn[i];
#pragma unroll
    for (int i = 0; i < 3; i++) T[i] = g_tn[i];
    float fx = Km[0], fy = Km[4], cx = Km[2], cy = Km[5];

    float Px = p3D[3 * ptc], Py = p3D[3 * ptc + 1], Pz = p3D[3 * ptc + 2];
    float x_ = R[0] * Px + R[1] * Py + R[2] * Pz + T[0];
    float y_ = R[3] * Px + R[4] * Py + R[5] * Pz + T[1];
    float d  = R[6] * Px + R[7] * Py + R[8] * Pz + T[2];
    float izd = 1.0f / d;
    float px = x_ * izd * fx + cx;
    float py = y_ * izd * fy + cy;
    bool valid = vp && inImage(px, py);
    if (!valid) { px = 256.0f; py = 256.0f; }

    int o[4]; float w[4];
    bilin4(px, py, o, w);
    const uint4* __restrict__ B = (const uint4*)g_fqH;
    float f8[8];
#pragma unroll
    for (int j = 0; j < 8; j++) f8[j] = 0.0f;
#pragma unroll
    for (int k = 0; k < 4; k++) {
        uint4 raw = __ldg(&B[o[k] + hl]);
        float p[8];
        unpack8(raw, p);
#pragma unroll
        for (int j = 0; j < 8; j++) f8[j] += w[k] * p[j];
    }
    float r8[8];
    {
        const float4* __restrict__ F4p = (const float4*)fref;
        float4 ra = __ldg(&F4p[ptc * 32 + 2 * hl]);
        float4 rb = __ldg(&F4p[ptc * 32 + 2 * hl + 1]);
        r8[0] = ra.x; r8[1] = ra.y; r8[2] = ra.z; r8[3] = ra.w;
        r8[4] = rb.x; r8[5] = rb.y; r8[6] = rb.z; r8[7] = rb.w;
    }
    float s[3] = {0.0f, 0.0f, 0.0f};
#pragma unroll
    for (int j = 0; j < 8; j++) {
        s[0] += f8[j] * f8[j];
        s[1] += f8[j] * r8[j];
        s[2] += r8[j] * r8[j];
    }
    halfReduce<3>(s);

    float inorm = 1.0f / fmaxf(sqrtf(s[0]), 1e-12f);
    float irn   = 1.0f / fmaxf(sqrtf(s[2]), 1e-12f);
    float errsq = s[0] * inorm * inorm - 2.0f * s[1] * inorm * irn + s[2] * irn * irn;
    float vf = valid ? 1.0f : 0.0f;

    double eD = (hl == 0) ? (double)(errsq * vf) : 0.0;
    double eC = (hl == 0) ? (double)vf : 0.0;
    eD += __shfl_down_sync(0xffffffffu, eD, 16);
    eC += __shfl_down_sync(0xffffffffu, eC, 16);

    __shared__ double sD[8], sC[8];
    if (lane == 0) { sD[warp] = eD; sC[warp] = eC; }
    __syncthreads();
    if (tid == 0) {
        double a = 0.0, b = 0.0;
#pragma unroll
        for (int i = 0; i < 8; i++) { a += sD[i]; b += sC[i]; }
        atomicAdd(&g_tacc[0], a);
        atomicAdd(&g_tacc[1], b);
    }
}

// ---------------- final costs + output ----------------
__global__ void __launch_bounds__(256) k_final(const float* __restrict__ p3D,
                                               const float* __restrict__ fref,
                                               const float* __restrict__ Km,
                                               int N, float* __restrict__ out) {
    int tid = threadIdx.x, lane = tid & 31, warp = tid >> 5;
    int hl = lane & 15, side = lane >> 4;
    int wid = blockIdx.x * 8 + warp;
    int pt = 2 * wid + side;
    bool vp = (pt < N);
    int ptc = vp ? pt : 0;

    double cn = g_tacc[0] / g_tacc[1];
    bool accPrev = (cn <= g_costbest);
    float R[9], T[3];
#pragma unroll
    for (int i = 0; i < 9; i++) R[i] = accPrev ? g_Rn[i] : g_R[i];
#pragma unroll
    for (int i = 0; i < 3; i++) T[i] = accPrev ? g_tn[i] : g_t[i];
    float fx = Km[0], fy = Km[4], cx = Km[2], cy = Km[5];

    if (blockIdx.x == 0 && tid == 0) {
#pragma unroll
        for (int i = 0; i < 9; i++) out[i] = R[i];
#pragma unroll
        for (int i = 0; i < 3; i++) out[9 + i] = T[i];
    }
    const float NANF = __int_as_float(0x7fc00000);

    float pix = g_p2init[2 * ptc], piy = g_p2init[2 * ptc + 1];
    float Px = p3D[3 * ptc], Py = p3D[3 * ptc + 1], Pz = p3D[3 * ptc + 2];
    float x_ = R[0] * Px + R[1] * Py + R[2] * Pz + T[0];
    float y_ = R[3] * Px + R[4] * Py + R[5] * Pz + T[1];
    float d  = R[6] * Px + R[7] * Py + R[8] * Pz + T[2];
    float izd = 1.0f / d;
    float pfx = x_ * izd * fx + cx;
    float pfy = y_ * izd * fy + cy;

    bool vi = inImage(pix, piy);
    bool vfv = inImage(pfx, pfy);
    float pixc = vi ? pix : 256.0f, piyc = vi ? piy : 256.0f;
    float pfxc = vfv ? pfx : 256.0f, pfyc = vfv ? pfy : 256.0f;

    int oi[4], of_[4];
    float wi[4], wf[4];
    bilin4(pixc, piyc, oi, wi);
    bilin4(pfxc, pfyc, of_, wf);

    const uint4* __restrict__ B = (const uint4*)g_fqH;
    float fi8[8], ff8[8];
#pragma unroll
    for (int j = 0; j < 8; j++) { fi8[j] = 0.0f; ff8[j] = 0.0f; }
#pragma unroll
    for (int k = 0; k < 4; k++) {
        uint4 rawi = __ldg(&B[oi[k] + hl]);
        uint4 rawf = __ldg(&B[of_[k] + hl]);
        float pi[8], pf[8];
        unpack8(rawi, pi);
        unpack8(rawf, pf);
#pragma unroll
        for (int j = 0; j < 8; j++) {
            fi8[j] += wi[k] * pi[j];
            ff8[j] += wf[k] * pf[j];
        }
    }
    float r8[8];
    {
        const float4* __restrict__ F4p = (const float4*)fref;
        float4 ra = __ldg(&F4p[ptc * 32 + 2 * hl]);
        float4 rb = __ldg(&F4p[ptc * 32 + 2 * hl + 1]);
        r8[0] = ra.x; r8[1] = ra.y; r8[2] = ra.z; r8[3] = ra.w;
        r8[4] = rb.x; r8[5] = rb.y; r8[6] = rb.z; r8[7] = rb.w;
    }
    float s[5] = {0, 0, 0, 0, 0};
#pragma unroll
    for (int j = 0; j < 8; j++) {
        s[0] += fi8[j] * fi8[j];
        s[1] += fi8[j] * r8[j];
        s[2] += ff8[j] * ff8[j];
        s[3] += ff8[j] * r8[j];
        s[4] += r8[j] * r8[j];
    }
    halfReduce<5>(s);

    if (hl == 0 && vp) {
        float irn = 1.0f / fmaxf(sqrtf(s[4]), 1e-12f);
        float ini = 1.0f / fmaxf(sqrtf(s[0]), 1e-12f);
        float inf_ = 1.0f / fmaxf(sqrtf(s[2]), 1e-12f);
        float rr = s[4] * irn * irn;
        float ci = rr - 2.0f * s[1] * ini * irn + s[0] * ini * ini;
        float cf = rr - 2.0f * s[3] * inf_ * irn + s[2] * inf_ * inf_;
        out[12 + pt]     = vi  ? ci : NANF;
        out[12 + N + pt] = vfv ? cf : NANF;
    }
}

// ---------------- launch ----------------
extern "C" void kernel_launch(void* const* d_in, const int* in_sizes, int n_in,
                              void* d_out, int out_size) {
    const float* p3D  = (const float*)d_in[0];
    const float* fref = (const float*)d_in[1];
    const float* fq   = (const float*)d_in[2];
    const float* Km   = (const float*)d_in[3];
    const float* R0   = (const float*)d_in[4];
    const float* t0   = (const float*)d_in[5];
    float* out = (float*)d_out;
    int N = in_sizes[0] / 3;
    if (N > MAXN) N = MAXN;

    int grid = (N + 15) / 16;   // 8 warps/block * 2 pts/warp
    k_init<<<1, 32>>>(R0, t0);
    k_transpose<<<NHW / 64, 256>>>(fq);
    for (int i = 0; i < 8; i++)
        k_main<<<grid, 256>>>(p3D, fref, Km, N, i);   // evaluates candidate c_i (c_0 = init)
    k_trial<<<grid, 256>>>(p3D, fref, Km, N);         // cost of c8 only
    k_final<<<grid, 256>>>(p3D, fref, Km, N, out);
}

// round 10
// speedup vs baseline: 1.6596x; 1.0385x over previous
#include <cuda_runtime.h>
#include <cuda_fp16.h>
#include <math.h>

#define NC   128
#define WW   512
#define HH   512
#define NHW  (HH*WW)
#define MAXN 10000

// ---------------- persistent device state ----------------
__device__ __align__(16) __half g_fqH[NC * NHW];  // (pixel, channel) layout, fp16
__device__ float  g_p2init[2 * MAXN];
__device__ double g_acc[29];    // [0..20] Hess uptri, [21..26] Grad, [27] cost, [28] count
__device__ double g_Hsav[27];   // H/G snapshot at last accepted pose
__device__ double g_tacc[2];    // final trial cost sum, count
__device__ double g_costbest;
__device__ float  g_R[9], g_t[3];     // accepted pose
__device__ float  g_Rn[9], g_tn[3];   // eval / candidate pose
__device__ float  g_lam, g_jac[6];
__device__ unsigned int g_count;

__constant__ int c_hi[21] = {0,0,0,0,0,0, 1,1,1,1,1, 2,2,2,2, 3,3,3, 4,4, 5};
__constant__ int c_hj[21] = {0,1,2,3,4,5, 1,2,3,4,5, 2,3,4,5, 3,4,5, 4,5, 5};

// ---------------- helpers ----------------
typedef unsigned long long u64t;

// packed f32x2 fused multiply-add (Blackwell): d = a*b + c, two fp32 lanes
__device__ __forceinline__ float2 ffma2(float2 a, float2 b, float2 c) {
    float2 d;
    asm("fma.rn.f32x2 %0, %1, %2, %3;"
        : "=l"(reinterpret_cast<u64t&>(d))
        : "l"(reinterpret_cast<const u64t&>(a)),
          "l"(reinterpret_cast<const u64t&>(b)),
          "l"(reinterpret_cast<const u64t&>(c)));
    return d;
}
__device__ __forceinline__ float2 bcast2(float w) { return make_float2(w, w); }
__device__ __forceinline__ float2 h2f2(unsigned int h) {
    return __half22float2(*(__half2*)&h);
}

__device__ __forceinline__ void unpack8(uint4 raw, float* p) {
    const __half2* h = (const __half2*)&raw;
#pragma unroll
    for (int j = 0; j < 4; j++) {
        float2 f = __half22float2(h[j]);
        p[2 * j]     = f.x;
        p[2 * j + 1] = f.y;
    }
}

template <int NV>
__device__ __forceinline__ void halfReduce(float* v) {
#pragma unroll
    for (int off = 8; off > 0; off >>= 1)
#pragma unroll
        for (int i = 0; i < NV; i++) v[i] += __shfl_xor_sync(0xffffffffu, v[i], off);
}

__device__ __forceinline__ float selJ0(int k, float fxz, float fxz2, float x, float y, float z) {
    switch (k) {
        case 0: return fxz;
        case 1: return 0.0f;
        case 2: return fxz2;
        case 3: return fxz2 * y;
        case 4: return fxz * z - fxz2 * x;
        default: return -fxz * y;
    }
}
__device__ __forceinline__ float selJ1(int k, float fyz, float fyz2, float x, float y, float z) {
    switch (k) {
        case 0: return 0.0f;
        case 1: return fyz;
        case 2: return fyz2;
        case 3: return -fyz * z + fyz2 * y;
        case 4: return -fyz2 * x;
        default: return fyz * x;
    }
}

__device__ __forceinline__ bool inImage(float px, float py) {
    return (px >= 1.0f) && (px < 511.0f) && (py >= 1.0f) && (py < 511.0f);
}

// bilinear footprint in uint4 (=8 half-channels) units: 16 per pixel
__device__ __forceinline__ void bilin4(float px, float py, int* o, float* w) {
    float x0f = fminf(fmaxf(floorf(px), 0.0f), 511.0f);
    float y0f = fminf(fmaxf(floorf(py), 0.0f), 511.0f);
    float x1f = fminf(x0f + 1.0f, 511.0f);
    float y1f = fminf(y0f + 1.0f, 511.0f);
    float wx = px - x0f, wy = py - y0f;
    int x0 = (int)x0f, x1 = (int)x1f, y0 = (int)y0f, y1 = (int)y1f;
    o[0] = (y0 * WW + x0) * 16;
    o[1] = (y0 * WW + x1) * 16;
    o[2] = (y1 * WW + x0) * 16;
    o[3] = (y1 * WW + x1) * 16;
    w[0] = (1.0f - wx) * (1.0f - wy);
    w[1] = wx * (1.0f - wy);
    w[2] = (1.0f - wx) * wy;
    w[3] = wx * wy;
}

// ---------------- init ----------------
__global__ void k_init(const float* __restrict__ R0, const float* __restrict__ t0) {
    int i = threadIdx.x;
    if (i < 9) { g_R[i] = R0[i]; g_Rn[i] = R0[i]; }
    if (i < 3) { g_t[i] = t0[i]; g_tn[i] = t0[i]; }
    if (i == 0) {
        g_lam = 0.01f; g_costbest = 0.0;
        g_tacc[0] = 0.0; g_tacc[1] = 1.0;
        g_count = 0u;
    }
    if (i < 29) g_acc[i] = 0.0;
}

// ---------------- transpose (C,H,W) f32 -> (H*W, C) f16 ----------------
__global__ void __launch_bounds__(256) k_transpose(const float* __restrict__ fq) {
    __shared__ float sh[64][NC + 1];
    int pix0 = blockIdx.x * 64;
    int tid = threadIdx.x;
    int px = tid & 63;
    int crow = tid >> 6;
#pragma unroll
    for (int cb = 0; cb < NC; cb += 4) {
        int c = cb + crow;
        sh[px][c] = fq[c * NHW + pix0 + px];
    }
    __syncthreads();
    int cpair = tid & 63;
    int prow = tid >> 6;
    __half2* out2 = (__half2*)g_fqH;
#pragma unroll
    for (int pb = 0; pb < 64; pb += 4) {
        int p = pb + prow;
        __half2 h = __floats2half2_rn(sh[p][2 * cpair], sh[p][2 * cpair + 1]);
        out2[(size_t)(pix0 + p) * 64 + cpair] = h;
    }
}

// ---------------- fused fp32 solve (one thread of last-arriving block) ----------------
__device__ void do_solve(int iter) {
    volatile double* acc = g_acc;
    double cn = acc[27] / acc[28];
    if (iter == 0) {
        g_costbest = cn;
        const int dix[6] = {0, 6, 11, 15, 18, 20};
#pragma unroll
        for (int i = 0; i < 6; i++) g_jac[i] = 1.0f / (1.0f + sqrtf((float)acc[dix[i]]));
#pragma unroll
        for (int i = 0; i < 27; i++) g_Hsav[i] = acc[i];
    } else {
        bool a = (cn <= g_costbest);
        float l = g_lam * (a ? 0.1f : 10.0f);
        g_lam = fminf(fmaxf(l, 1e-8f), 1e4f);
        if (a) {
            g_costbest = cn;
#pragma unroll
            for (int i = 0; i < 9; i++) g_R[i] = g_Rn[i];
#pragma unroll
            for (int i = 0; i < 3; i++) g_t[i] = g_tn[i];
#pragma unroll
            for (int i = 0; i < 27; i++) g_Hsav[i] = acc[i];
        }
    }

    float jac[6];
#pragma unroll
    for (int i = 0; i < 6; i++) jac[i] = g_jac[i];

    float A[6][7];
    {
        int idx = 0;
#pragma unroll
        for (int i = 0; i < 6; i++)
#pragma unroll
            for (int j = i; j < 6; j++) {
                float v = (float)g_Hsav[idx++] * jac[i] * jac[j];
                A[i][j] = v;
                A[j][i] = v;
            }
    }
    float lam = g_lam;
#pragma unroll
    for (int i = 0; i < 6; i++) {
        float d = A[i][i];
        A[i][i] = d + (d + 1e-9f) * lam;
        A[i][6] = -(float)g_Hsav[21 + i] * jac[i];
    }
    for (int col = 0; col < 6; col++) {
        int piv = col;
        float best = fabsf(A[col][col]);
        for (int r = col + 1; r < 6; r++) {
            float v = fabsf(A[r][col]);
            if (v > best) { best = v; piv = r; }
        }
        if (piv != col)
            for (int j = 0; j < 7; j++) { float t = A[col][j]; A[col][j] = A[piv][j]; A[piv][j] = t; }
        float ip = 1.0f / A[col][col];
        for (int r = col + 1; r < 6; r++) {
            float f = A[r][col] * ip;
            for (int j = col; j < 7; j++) A[r][j] -= f * A[col][j];
        }
    }
    float x[6];
#pragma unroll
    for (int i = 5; i >= 0; i--) {
        float v = A[i][6];
#pragma unroll
        for (int j = 0; j < 6; j++)
            if (j > i) v -= A[i][j] * x[j];
        x[i] = v / A[i][i];
    }
    float delta[6];
#pragma unroll
    for (int i = 0; i < 6; i++) delta[i] = x[i] * jac[i];

    float w0 = delta[3], w1 = delta[4], w2 = delta[5];
    float th2 = w0 * w0 + w1 * w1 + w2 * w2;
    float th = sqrtf(th2);
    float Ac, Bc;
    if (th < 1e-7f) { Ac = 1.0f; Bc = 0.5f; }
    else            { Ac = sinf(th) / th; Bc = (1.0f - cosf(th)) / th2; }
    float Wm[9] = {0.0f, -w2, w1, w2, 0.0f, -w0, -w1, w0, 0.0f};
    float W2[9];
#pragma unroll
    for (int i = 0; i < 3; i++)
#pragma unroll
        for (int j = 0; j < 3; j++) {
            float s2 = 0.0f;
#pragma unroll
            for (int k = 0; k < 3; k++) s2 += Wm[i * 3 + k] * Wm[k * 3 + j];
            W2[i * 3 + j] = s2;
        }
    float dr[9];
#pragma unroll
    for (int i = 0; i < 9; i++)
        dr[i] = ((i % 4) == 0 ? 1.0f : 0.0f) + Ac * Wm[i] + Bc * W2[i];

    float Rl[9], Tl[3];
#pragma unroll
    for (int i = 0; i < 9; i++) Rl[i] = g_R[i];
#pragma unroll
    for (int i = 0; i < 3; i++) Tl[i] = g_t[i];
#pragma unroll
    for (int i = 0; i < 3; i++) {
#pragma unroll
        for (int j = 0; j < 3; j++) {
            float s2 = 0.0f;
#pragma unroll
            for (int k = 0; k < 3; k++) s2 += dr[i * 3 + k] * Rl[k * 3 + j];
            g_Rn[i * 3 + j] = s2;
        }
        g_tn[i] = dr[i * 3] * Tl[0] + dr[i * 3 + 1] * Tl[1] + dr[i * 3 + 2] * Tl[2] + delta[i];
    }
#pragma unroll
    for (int i = 0; i < 29; i++) g_acc[i] = 0.0;
    g_count = 0u;
}

// accumulator slot value (0..28) for one point
__device__ __forceinline__ float valForIdx(int idx, float Mxx, float Mxy, float Myy,
                                           float g2x, float g2y, float errsq,
                                           float fxz, float fxz2, float fyz, float fyz2,
                                           float x_, float y_, float d) {
    if (idx < 21) {
        int i = c_hi[idx], j = c_hj[idx];
        float a0 = selJ0(i, fxz, fxz2, x_, y_, d);
        float a1 = selJ1(i, fyz, fyz2, x_, y_, d);
        float b0 = selJ0(j, fxz, fxz2, x_, y_, d);
        float b1 = selJ1(j, fyz, fyz2, x_, y_, d);
        float u  = Mxx * a0 + Mxy * a1;
        float vv = Mxy * a0 + Myy * a1;
        return u * b0 + vv * b1;
    } else if (idx < 27) {
        int j = idx - 21;
        float b0 = selJ0(j, fxz, fxz2, x_, y_, d);
        float b1 = selJ1(j, fyz, fyz2, x_, y_, d);
        return g2x * b0 + g2y * b1;
    } else if (idx == 27) {
        return errsq;
    }
    return 1.0f;
}

// ---------------- main LM accumulation at candidate pose (+ fused solve) ----------------
__global__ void __launch_bounds__(256, 3) k_main(const float* __restrict__ p3D,
                                                 const float* __restrict__ fref,
                                                 const float* __restrict__ Km,
                                                 int N, int iter) {
    int tid = threadIdx.x, lane = tid & 31, warp = tid >> 5;
    int hl = lane & 15;
    int side = lane >> 4;
    int wid = blockIdx.x * 8 + warp;
    int pt = 2 * wid + side;
    bool vp = (pt < N);
    int ptc = vp ? pt : 0;

    float R[9], T[3];
#pragma unroll
    for (int i = 0; i < 9; i++) R[i] = g_Rn[i];
#pragma unroll
    for (int i = 0; i < 3; i++) T[i] = g_tn[i];
    float fx = Km[0], fy = Km[4], cx = Km[2], cy = Km[5];

    float Px = p3D[3 * ptc], Py = p3D[3 * ptc + 1], Pz = p3D[3 * ptc + 2];
    float x_ = R[0] * Px + R[1] * Py + R[2] * Pz + T[0];
    float y_ = R[3] * Px + R[4] * Py + R[5] * Pz + T[1];
    float d  = R[6] * Px + R[7] * Py + R[8] * Pz + T[2];
    float izd0 = 1.0f / d;
    float px = x_ * izd0 * fx + cx;
    float py = y_ * izd0 * fy + cy;
    if (iter == 0 && hl == 0 && vp) { g_p2init[2 * pt] = px; g_p2init[2 * pt + 1] = py; }
    bool valid = vp && inImage(px, py);
    if (!valid) { px = 256.0f; py = 256.0f; d = 1.0f; }
    float izd = 1.0f / d;

    float x0f = floorf(px), y0f = floorf(py);
    float wx = px - x0f, wy = py - y0f;
    int x0 = (int)x0f, x1 = x0 + 1, y0 = (int)y0f, y1 = y0 + 1;
    int colo[4] = {(x0 - 1) * 16, x0 * 16, x1 * 16, (x1 < 511 ? x1 + 1 : 511) * 16};
    int rowo[4] = {(y0 - 1) * (WW * 16), y0 * (WW * 16), y1 * (WW * 16),
                   (y1 < 511 ? y1 + 1 : 511) * (WW * 16)};

    // separable sobel x bilinear weights: wgx=Ay8[i]Bx[j], wgy=By8[i]Ax[j]
    float Ax[4]  = {1.0f - wx, 2.0f - wx, 1.0f + wx, wx};
    float Bx[4]  = {-(1.0f - wx), -wx, 1.0f - wx, wx};
    float Ay8[4] = {(1.0f - wy) * 0.125f, (2.0f - wy) * 0.125f,
                    (1.0f + wy) * 0.125f, wy * 0.125f};
    float By8[4] = {-(1.0f - wy) * 0.125f, -wy * 0.125f,
                    (1.0f - wy) * 0.125f, wy * 0.125f};
    float fxw0 = 1.0f - wx, fyw0 = 1.0f - wy;

    const uint4* __restrict__ B = (const uint4*)g_fqH;
    // packed float2 lanes: 4 x float2 = 8 channels per thread
    float2 f2[4], gx2[4], gy2[4];
#pragma unroll
    for (int q = 0; q < 4; q++) {
        f2[q] = make_float2(0.f, 0.f);
        gx2[q] = make_float2(0.f, 0.f);
        gy2[q] = make_float2(0.f, 0.f);
    }
#pragma unroll
    for (int i = 0; i < 4; i++) {
        float2 rx2[4], ra2[4];
#pragma unroll
        for (int q = 0; q < 4; q++) { rx2[q] = make_float2(0.f, 0.f); ra2[q] = make_float2(0.f, 0.f); }
#pragma unroll
        for (int j = 0; j < 4; j++) {
            uint4 raw = __ldg(&B[rowo[i] + colo[j] + hl]);
            float2 p2[4];
            p2[0] = h2f2(raw.x); p2[1] = h2f2(raw.y);
            p2[2] = h2f2(raw.z); p2[3] = h2f2(raw.w);
            float2 bx = bcast2(Bx[j]), ax = bcast2(Ax[j]);
#pragma unroll
            for (int q = 0; q < 4; q++) {
                rx2[q] = ffma2(bx, p2[q], rx2[q]);
                ra2[q] = ffma2(ax, p2[q], ra2[q]);
            }
            if ((i == 1 || i == 2) && (j == 1 || j == 2)) {
                float2 wc = bcast2(((j == 1) ? fxw0 : wx) * ((i == 1) ? fyw0 : wy));
#pragma unroll
                for (int q = 0; q < 4; q++) f2[q] = ffma2(wc, p2[q], f2[q]);
            }
        }
        float2 ay = bcast2(Ay8[i]), by = bcast2(By8[i]);
#pragma unroll
        for (int q = 0; q < 4; q++) {
            gx2[q] = ffma2(ay, rx2[q], gx2[q]);
            gy2[q] = ffma2(by, ra2[q], gy2[q]);
        }
    }
    float2 r2[4];
    {
        const float4* __restrict__ F4p = (const float4*)fref;
        float4 ra4 = __ldg(&F4p[ptc * 32 + 2 * hl]);
        float4 rb4 = __ldg(&F4p[ptc * 32 + 2 * hl + 1]);
        r2[0] = make_float2(ra4.x, ra4.y);
        r2[1] = make_float2(ra4.z, ra4.w);
        r2[2] = make_float2(rb4.x, rb4.y);
        r2[3] = make_float2(rb4.z, rb4.w);
    }

    float2 t2[10];
#pragma unroll
    for (int i = 0; i < 10; i++) t2[i] = make_float2(0.f, 0.f);
#pragma unroll
    for (int q = 0; q < 4; q++) {
        t2[0] = ffma2(f2[q], f2[q], t2[0]);
        t2[1] = ffma2(f2[q], gx2[q], t2[1]);
        t2[2] = ffma2(f2[q], gy2[q], t2[2]);
        t2[3] = ffma2(gx2[q], gx2[q], t2[3]);
        t2[4] = ffma2(gx2[q], gy2[q], t2[4]);
        t2[5] = ffma2(gy2[q], gy2[q], t2[5]);
        t2[6] = ffma2(gx2[q], r2[q], t2[6]);
        t2[7] = ffma2(gy2[q], r2[q], t2[7]);
        t2[8] = ffma2(f2[q], r2[q], t2[8]);
        t2[9] = ffma2(r2[q], r2[q], t2[9]);
    }
    float s[10];
#pragma unroll
    for (int i = 0; i < 10; i++) s[i] = t2[i].x + t2[i].y;
    halfReduce<10>(s);

    float norm  = fmaxf(sqrtf(s[0]), 1e-12f);
    float rnorm = fmaxf(sqrtf(s[9]), 1e-12f);
    float inorm = 1.0f / norm, irn = 1.0f / rnorm;
    float projx = s[1] * inorm, projy = s[2] * inorm;
    float nf2 = s[0] * inorm * inorm;
    float sc  = s[8] * inorm * irn;
    float in2 = inorm * inorm;
    float fac = 2.0f - nf2;
    float Mxx = (s[3] - projx * projx * fac) * in2;
    float Mxy = (s[4] - projx * projy * fac) * in2;
    float Myy = (s[5] - projy * projy * fac) * in2;
    float coef = 1.0f - nf2 + sc;
    float g2x = (projx * coef - s[6] * irn) * inorm;
    float g2y = (projy * coef - s[7] * irn) * inorm;
    float errsq = nf2 - 2.0f * sc + s[9] * irn * irn;

    float fxz = fx * izd, fxz2 = -fx * x_ * izd * izd;
    float fyz = fy * izd, fyz2 = -fy * y_ * izd * izd;
    float vf = valid ? 1.0f : 0.0f;

    double a0 = (double)(vf * valForIdx(hl, Mxx, Mxy, Myy, g2x, g2y, errsq,
                                        fxz, fxz2, fyz, fyz2, x_, y_, d));
    double a1 = 0.0;
    if (hl < 13)
        a1 = (double)(vf * valForIdx(hl + 16, Mxx, Mxy, Myy, g2x, g2y, errsq,
                                     fxz, fxz2, fyz, fyz2, x_, y_, d));
    a0 += __shfl_down_sync(0xffffffffu, a0, 16);
    a1 += __shfl_down_sync(0xffffffffu, a1, 16);

    __shared__ double sred[8][29];
    __shared__ bool s_last;
    if (lane < 16) sred[warp][lane] = a0;
    if (lane < 13) sred[warp][16 + lane] = a1;
    __syncthreads();
    if (warp == 0 && lane < 29) {
        double tt = 0.0;
#pragma unroll
        for (int w2i = 0; w2i < 8; w2i++) tt += sred[w2i][lane];
        atomicAdd(&g_acc[lane], tt);
    }
    __syncthreads();
    if (tid == 0) {
        __threadfence();
        unsigned int t = atomicAdd(&g_count, 1u);
        s_last = (t == gridDim.x - 1);
    }
    __syncthreads();
    if (s_last && tid == 0) {
        __threadfence();
        do_solve(iter);
    }
}

// ---------------- trial cost of final candidate c8 ----------------
__global__ void __launch_bounds__(256) k_trial(const float* __restrict__ p3D,
                                               const float* __restrict__ fref,
                                               const float* __restrict__ Km, int N) {
    int tid = threadIdx.x, lane = tid & 31, warp = tid >> 5;
    int hl = lane & 15, side = lane >> 4;
    int wid = blockIdx.x * 8 + warp;
    int pt = 2 * wid + side;
    bool vp = (pt < N);
    int ptc = vp ? pt : 0;

    float R[9], T[3];
#pragma unroll
    for (int i = 0; i < 9; i++) R[i] = g_Rn[i];
#pragma unroll
    for (int i = 0; i < 3; i++) T[i] = g_tn[i];
    float fx = Km[0], fy = Km[4], cx = Km[2], cy = Km[5];

    float Px = p3D[3 * ptc], Py = p3D[3 * ptc + 1], Pz = p3D[3 * ptc + 2];
    float x_ = R[0] * Px + R[1] * Py + R[2] * Pz + T[0];
    float y_ = R[3] * Px + R[4] * Py + R[5] * Pz + T[1];
    float d  = R[6] * Px + R[7] * Py + R[8] * Pz + T[2];
    float izd = 1.0f / d;
    float px = x_ * izd * fx + cx;
    float py = y_ * izd * fy + cy;
    bool valid = vp && inImage(px, py);
    if (!valid) { px = 256.0f; py = 256.0f; }

    int o[4]; float w[4];
    bilin4(px, py, o, w);
    const uint4* __restrict__ B = (const uint4*)g_fqH;
    float f8[8];
#pragma unroll
    for (int j = 0; j < 8; j++) f8[j] = 0.0f;
#pragma unroll
    for (int k = 0; k < 4; k++) {
        uint4 raw = __ldg(&B[o[k] + hl]);
        float p[8];
        unpack8(raw, p);
#pragma unroll
        for (int j = 0; j < 8; j++) f8[j] += w[k] * p[j];
    }
    float r8[8];
    {
        const float4* __restrict__ F4p = (const float4*)fref;
        float4 ra = __ldg(&F4p[ptc * 32 + 2 * hl]);
        float4 rb = __ldg(&F4p[ptc * 32 + 2 * hl + 1]);
        r8[0] = ra.x; r8[1] = ra.y; r8[2] = ra.z; r8[3] = ra.w;
        r8[4] = rb.x; r8[5] = rb.y; r8[6] = rb.z; r8[7] = rb.w;
    }
    float s[3] = {0.0f, 0.0f, 0.0f};
#pragma unroll
    for (int j = 0; j < 8; j++) {
        s[0] += f8[j] * f8[j];
        s[1] += f8[j] * r8[j];
        s[2] += r8[j] * r8[j];
    }
    halfReduce<3>(s);

    float inorm = 1.0f / fmaxf(sqrtf(s[0]), 1e-12f);
    float irn   = 1.0f / fmaxf(sqrtf(s[2]), 1e-12f);
    float errsq = s[0] * inorm * inorm - 2.0f * s[1] * inorm * irn + s[2] * irn * irn;
    float vf = valid ? 1.0f : 0.0f;

    double eD = (hl == 0) ? (double)(errsq * vf) : 0.0;
    double eC = (hl == 0) ? (double)vf : 0.0;
    eD += __shfl_down_sync(0xffffffffu, eD, 16);
    eC += __shfl_down_sync(0xffffffffu, eC, 16);

    __shared__ double sD[8], sC[8];
    if (lane == 0) { sD[warp] = eD; sC[warp] = eC; }
    __syncthreads();
    if (tid == 0) {
        double a = 0.0, b = 0.0;
#pragma unroll
        for (int i = 0; i < 8; i++) { a += sD[i]; b += sC[i]; }
        atomicAdd(&g_tacc[0], a);
        atomicAdd(&g_tacc[1], b);
    }
}

// ---------------- final costs + output ----------------
__global__ void __launch_bounds__(256) k_final(const float* __restrict__ p3D,
                                               const float* __restrict__ fref,
                                               const float* __restrict__ Km,
                                               int N, float* __restrict__ out) {
    int tid = threadIdx.x, lane = tid & 31, warp = tid >> 5;
    int hl = lane & 15, side = lane >> 4;
    int wid = blockIdx.x * 8 + warp;
    int pt = 2 * wid + side;
    bool vp = (pt < N);
    int ptc = vp ? pt : 0;

    double cn = g_tacc[0] / g_tacc[1];
    bool accPrev = (cn <= g_costbest);
    float R[9], T[3];
#pragma unroll
    for (int i = 0; i < 9; i++) R[i] = accPrev ? g_Rn[i] : g_R[i];
#pragma unroll
    for (int i = 0; i < 3; i++) T[i] = accPrev ? g_tn[i] : g_t[i];
    float fx = Km[0], fy = Km[4], cx = Km[2], cy = Km[5];

    if (blockIdx.x == 0 && tid == 0) {
#pragma unroll
        for (int i = 0; i < 9; i++) out[i] = R[i];
#pragma unroll
        for (int i = 0; i < 3; i++) out[9 + i] = T[i];
    }
    const float NANF = __int_as_float(0x7fc00000);

    float pix = g_p2init[2 * ptc], piy = g_p2init[2 * ptc + 1];
    float Px = p3D[3 * ptc], Py = p3D[3 * ptc + 1], Pz = p3D[3 * ptc + 2];
    float x_ = R[0] * Px + R[1] * Py + R[2] * Pz + T[0];
    float y_ = R[3] * Px + R[4] * Py + R[5] * Pz + T[1];
    float d  = R[6] * Px + R[7] * Py + R[8] * Pz + T[2];
    float izd = 1.0f / d;
    float pfx = x_ * izd * fx + cx;
    float pfy = y_ * izd * fy + cy;

    bool vi = inImage(pix, piy);
    bool vfv = inImage(pfx, pfy);
    float pixc = vi ? pix : 256.0f, piyc = vi ? piy : 256.0f;
    float pfxc = vfv ? pfx : 256.0f, pfyc = vfv ? pfy : 256.0f;

    int oi[4], of_[4];
    float wi[4], wf[4];
    bilin4(pixc, piyc, oi, wi);
    bilin4(pfxc, pfyc, of_, wf);

    const uint4* __restrict__ B = (const uint4*)g_fqH;
    float fi8[8], ff8[8];
#pragma unroll
    for (int j = 0; j < 8; j++) { fi8[j] = 0.0f; ff8[j] = 0.0f; }
#pragma unroll
    for (int k = 0; k < 4; k++) {
        uint4 rawi = __ldg(&B[oi[k] + hl]);
        uint4 rawf = __ldg(&B[of_[k] + hl]);
        float pi[8], pf[8];
        unpack8(rawi, pi);
        unpack8(rawf, pf);
#pragma unroll
        for (int j = 0; j < 8; j++) {
            fi8[j] += wi[k] * pi[j];
            ff8[j] += wf[k] * pf[j];
        }
    }
    float r8[8];
    {
        const float4* __restrict__ F4p = (const float4*)fref;
        float4 ra = __ldg(&F4p[ptc * 32 + 2 * hl]);
        float4 rb = __ldg(&F4p[ptc * 32 + 2 * hl + 1]);
        r8[0] = ra.x; r8[1] = ra.y; r8[2] = ra.z; r8[3] = ra.w;
        r8[4] = rb.x; r8[5] = rb.y; r8[6] = rb.z; r8[7] = rb.w;
    }
    float s[5] = {0, 0, 0, 0, 0};
#pragma unroll
    for (int j = 0; j < 8; j++) {
        s[0] += fi8[j] * fi8[j];
        s[1] += fi8[j] * r8[j];
        s[2] += ff8[j] * ff8[j];
        s[3] += ff8[j] * r8[j];
        s[4] += r8[j] * r8[j];
    }
    halfReduce<5>(s);

    if (hl == 0 && vp) {
        float irn = 1.0f / fmaxf(sqrtf(s[4]), 1e-12f);
        float ini = 1.0f / fmaxf(sqrtf(s[0]), 1e-12f);
        float inf_ = 1.0f / fmaxf(sqrtf(s[2]), 1e-12f);
        float rr = s[4] * irn * irn;
        float ci = rr - 2.0f * s[1] * ini * irn + s[0] * ini * ini;
        float cf = rr - 2.0f * s[3] * inf_ * irn + s[2] * inf_ * inf_;
        out[12 + pt]     = vi  ? ci : NANF;
        out[12 + N + pt] = vfv ? cf : NANF;
    }
}

// ---------------- launch ----------------
extern "C" void kernel_launch(void* const* d_in, const int* in_sizes, int n_in,
                              void* d_out, int out_size) {
    const float* p3D  = (const float*)d_in[0];
    const float* fref = (const float*)d_in[1];
    const float* fq   = (const float*)d_in[2];
    const float* Km   = (const float*)d_in[3];
    const float* R0   = (const float*)d_in[4];
    const float* t0   = (const float*)d_in[5];
    float* out = (float*)d_out;
    int N = in_sizes[0] / 3;
    if (N > MAXN) N = MAXN;

    int grid = (N + 15) / 16;   // 8 warps/block * 2 pts/warp
    k_init<<<1, 32>>>(R0, t0);
    k_transpose<<<NHW / 64, 256>>>(fq);
    for (int i = 0; i < 8; i++)
        k_main<<<grid, 256>>>(p3D, fref, Km, N, i);   // evaluates candidate c_i (c_0 = init)
    k_trial<<<grid, 256>>>(p3D, fref, Km, N);         // cost of c8 only
    k_final<<<grid, 256>>>(p3D, fref, Km, N, out);
}

// round 11
// speedup vs baseline: 1.6940x; 1.0207x over previous
#include <cuda_runtime.h>
#include <cuda_fp16.h>
#include <math.h>

#define NC   128
#define WW   512
#define HH   512
#define NHW  (HH*WW)
#define MAXN 10000
#define PGRID 313   // single wave (<=444 resident at 80 regs); 313*8*2*2 >= 10000

// ---------------- persistent device state ----------------
__device__ __align__(16) __half g_fqH[NC * NHW];  // (pixel, channel) layout, fp16
__device__ float  g_p2init[2 * MAXN];
__device__ double g_acc[29];    // [0..20] Hess uptri, [21..26] Grad, [27] cost, [28] count
__device__ double g_Hsav[27];   // H/G snapshot at last accepted pose
__device__ double g_tacc[2];    // final trial cost sum, count
__device__ double g_costbest;
__device__ float  g_R[9], g_t[3];     // accepted pose
__device__ float  g_Rn[9], g_tn[3];   // eval / candidate pose
__device__ float  g_lam, g_jac[6];
__device__ unsigned int g_count;

__constant__ int c_hi[21] = {0,0,0,0,0,0, 1,1,1,1,1, 2,2,2,2, 3,3,3, 4,4, 5};
__constant__ int c_hj[21] = {0,1,2,3,4,5, 1,2,3,4,5, 2,3,4,5, 3,4,5, 4,5, 5};

// ---------------- helpers ----------------
typedef unsigned long long u64t;

__device__ __forceinline__ float2 ffma2(float2 a, float2 b, float2 c) {
    float2 d;
    asm("fma.rn.f32x2 %0, %1, %2, %3;"
        : "=l"(reinterpret_cast<u64t&>(d))
        : "l"(reinterpret_cast<const u64t&>(a)),
          "l"(reinterpret_cast<const u64t&>(b)),
          "l"(reinterpret_cast<const u64t&>(c)));
    return d;
}
__device__ __forceinline__ float2 bcast2(float w) { return make_float2(w, w); }
__device__ __forceinline__ float2 h2f2(unsigned int h) {
    return __half22float2(*(__half2*)&h);
}

__device__ __forceinline__ void unpack8(uint4 raw, float* p) {
    const __half2* h = (const __half2*)&raw;
#pragma unroll
    for (int j = 0; j < 4; j++) {
        float2 f = __half22float2(h[j]);
        p[2 * j]     = f.x;
        p[2 * j + 1] = f.y;
    }
}

template <int NV>
__device__ __forceinline__ void halfReduce(float* v) {
#pragma unroll
    for (int off = 8; off > 0; off >>= 1)
#pragma unroll
        for (int i = 0; i < NV; i++) v[i] += __shfl_xor_sync(0xffffffffu, v[i], off);
}

__device__ __forceinline__ float selJ0(int k, float fxz, float fxz2, float x, float y, float z) {
    switch (k) {
        case 0: return fxz;
        case 1: return 0.0f;
        case 2: return fxz2;
        case 3: return fxz2 * y;
        case 4: return fxz * z - fxz2 * x;
        default: return -fxz * y;
    }
}
__device__ __forceinline__ float selJ1(int k, float fyz, float fyz2, float x, float y, float z) {
    switch (k) {
        case 0: return 0.0f;
        case 1: return fyz;
        case 2: return fyz2;
        case 3: return -fyz * z + fyz2 * y;
        case 4: return -fyz2 * x;
        default: return fyz * x;
    }
}

__device__ __forceinline__ bool inImage(float px, float py) {
    return (px >= 1.0f) && (px < 511.0f) && (py >= 1.0f) && (py < 511.0f);
}

// bilinear footprint in uint4 (=8 half-channels) units: 16 per pixel
__device__ __forceinline__ void bilin4(float px, float py, int* o, float* w) {
    float x0f = fminf(fmaxf(floorf(px), 0.0f), 511.0f);
    float y0f = fminf(fmaxf(floorf(py), 0.0f), 511.0f);
    float x1f = fminf(x0f + 1.0f, 511.0f);
    float y1f = fminf(y0f + 1.0f, 511.0f);
    float wx = px - x0f, wy = py - y0f;
    int x0 = (int)x0f, x1 = (int)x1f, y0 = (int)y0f, y1 = (int)y1f;
    o[0] = (y0 * WW + x0) * 16;
    o[1] = (y0 * WW + x1) * 16;
    o[2] = (y1 * WW + x0) * 16;
    o[3] = (y1 * WW + x1) * 16;
    w[0] = (1.0f - wx) * (1.0f - wy);
    w[1] = wx * (1.0f - wy);
    w[2] = (1.0f - wx) * wy;
    w[3] = wx * wy;
}

// ---------------- init ----------------
__global__ void k_init(const float* __restrict__ R0, const float* __restrict__ t0) {
    int i = threadIdx.x;
    if (i < 9) { g_R[i] = R0[i]; g_Rn[i] = R0[i]; }
    if (i < 3) { g_t[i] = t0[i]; g_tn[i] = t0[i]; }
    if (i == 0) {
        g_lam = 0.01f; g_costbest = 0.0;
        g_tacc[0] = 0.0; g_tacc[1] = 1.0;
        g_count = 0u;
    }
    if (i < 29) g_acc[i] = 0.0;
}

// ---------------- transpose (C,H,W) f32 -> (H*W, C) f16, vectorized ----------------
__global__ void __launch_bounds__(256) k_transpose(const float* __restrict__ fq) {
    __shared__ float sh[64][NC + 1];
    int pix0 = blockIdx.x * 64;
    int tid = threadIdx.x;
    // phase 1: float4 loads — 16 float4 (=64 px) x 16 channels per pass
    int px4 = tid & 15;
    int c0 = tid >> 4;
    const float4* __restrict__ fq4 = (const float4*)fq;
#pragma unroll
    for (int cb = 0; cb < NC; cb += 16) {
        int c = cb + c0;
        float4 v = __ldg(&fq4[(size_t)c * (NHW / 4) + (pix0 >> 2) + px4]);
        sh[4 * px4 + 0][c] = v.x;
        sh[4 * px4 + 1][c] = v.y;
        sh[4 * px4 + 2][c] = v.z;
        sh[4 * px4 + 3][c] = v.w;
    }
    __syncthreads();
    // phase 2: uint4 stores — 16 uint4 (=128 half) per pixel, 16 pixels per pass
    int cq = tid & 15;
    int prow = tid >> 4;
    uint4* out4 = (uint4*)g_fqH;
#pragma unroll
    for (int pb = 0; pb < 64; pb += 16) {
        int p = pb + prow;
        const float* row = &sh[p][8 * cq];
        uint4 v;
        __half2 h0 = __floats2half2_rn(row[0], row[1]);
        __half2 h1 = __floats2half2_rn(row[2], row[3]);
        __half2 h2 = __floats2half2_rn(row[4], row[5]);
        __half2 h3 = __floats2half2_rn(row[6], row[7]);
        v.x = *(unsigned int*)&h0;
        v.y = *(unsigned int*)&h1;
        v.z = *(unsigned int*)&h2;
        v.w = *(unsigned int*)&h3;
        out4[(size_t)(pix0 + p) * 16 + cq] = v;
    }
}

// ---------------- fused fp32 solve (one thread of last-arriving block) ----------------
__device__ void do_solve(int iter) {
    volatile double* acc = g_acc;
    double cn = acc[27] / acc[28];
    if (iter == 0) {
        g_costbest = cn;
        const int dix[6] = {0, 6, 11, 15, 18, 20};
#pragma unroll
        for (int i = 0; i < 6; i++) g_jac[i] = 1.0f / (1.0f + sqrtf((float)acc[dix[i]]));
#pragma unroll
        for (int i = 0; i < 27; i++) g_Hsav[i] = acc[i];
    } else {
        bool a = (cn <= g_costbest);
        float l = g_lam * (a ? 0.1f : 10.0f);
        g_lam = fminf(fmaxf(l, 1e-8f), 1e4f);
        if (a) {
            g_costbest = cn;
#pragma unroll
            for (int i = 0; i < 9; i++) g_R[i] = g_Rn[i];
#pragma unroll
            for (int i = 0; i < 3; i++) g_t[i] = g_tn[i];
#pragma unroll
            for (int i = 0; i < 27; i++) g_Hsav[i] = acc[i];
        }
    }

    float jac[6];
#pragma unroll
    for (int i = 0; i < 6; i++) jac[i] = g_jac[i];

    float A[6][7];
    {
        int idx = 0;
#pragma unroll
        for (int i = 0; i < 6; i++)
#pragma unroll
            for (int j = i; j < 6; j++) {
                float v = (float)g_Hsav[idx++] * jac[i] * jac[j];
                A[i][j] = v;
                A[j][i] = v;
            }
    }
    float lam = g_lam;
#pragma unroll
    for (int i = 0; i < 6; i++) {
        float d = A[i][i];
        A[i][i] = d + (d + 1e-9f) * lam;
        A[i][6] = -(float)g_Hsav[21 + i] * jac[i];
    }
    for (int col = 0; col < 6; col++) {
        int piv = col;
        float best = fabsf(A[col][col]);
        for (int r = col + 1; r < 6; r++) {
            float v = fabsf(A[r][col]);
            if (v > best) { best = v; piv = r; }
        }
        if (piv != col)
            for (int j = 0; j < 7; j++) { float t = A[col][j]; A[col][j] = A[piv][j]; A[piv][j] = t; }
        float ip = 1.0f / A[col][col];
        for (int r = col + 1; r < 6; r++) {
            float f = A[r][col] * ip;
            for (int j = col; j < 7; j++) A[r][j] -= f * A[col][j];
        }
    }
    float x[6];
#pragma unroll
    for (int i = 5; i >= 0; i--) {
        float v = A[i][6];
#pragma unroll
        for (int j = 0; j < 6; j++)
            if (j > i) v -= A[i][j] * x[j];
        x[i] = v / A[i][i];
    }
    float delta[6];
#pragma unroll
    for (int i = 0; i < 6; i++) delta[i] = x[i] * jac[i];

    float w0 = delta[3], w1 = delta[4], w2 = delta[5];
    float th2 = w0 * w0 + w1 * w1 + w2 * w2;
    float th = sqrtf(th2);
    float Ac, Bc;
    if (th < 1e-7f) { Ac = 1.0f; Bc = 0.5f; }
    else            { Ac = sinf(th) / th; Bc = (1.0f - cosf(th)) / th2; }
    float Wm[9] = {0.0f, -w2, w1, w2, 0.0f, -w0, -w1, w0, 0.0f};
    float W2[9];
#pragma unroll
    for (int i = 0; i < 3; i++)
#pragma unroll
        for (int j = 0; j < 3; j++) {
            float s2 = 0.0f;
#pragma unroll
            for (int k = 0; k < 3; k++) s2 += Wm[i * 3 + k] * Wm[k * 3 + j];
            W2[i * 3 + j] = s2;
        }
    float dr[9];
#pragma unroll
    for (int i = 0; i < 9; i++)
        dr[i] = ((i % 4) == 0 ? 1.0f : 0.0f) + Ac * Wm[i] + Bc * W2[i];

    float Rl[9], Tl[3];
#pragma unroll
    for (int i = 0; i < 9; i++) Rl[i] = g_R[i];
#pragma unroll
    for (int i = 0; i < 3; i++) Tl[i] = g_t[i];
#pragma unroll
    for (int i = 0; i < 3; i++) {
#pragma unroll
        for (int j = 0; j < 3; j++) {
            float s2 = 0.0f;
#pragma unroll
            for (int k = 0; k < 3; k++) s2 += dr[i * 3 + k] * Rl[k * 3 + j];
            g_Rn[i * 3 + j] = s2;
        }
        g_tn[i] = dr[i * 3] * Tl[0] + dr[i * 3 + 1] * Tl[1] + dr[i * 3 + 2] * Tl[2] + delta[i];
    }
#pragma unroll
    for (int i = 0; i < 29; i++) g_acc[i] = 0.0;
    g_count = 0u;
}

// accumulator slot value (0..28) for one point
__device__ __forceinline__ float valForIdx(int idx, float Mxx, float Mxy, float Myy,
                                           float g2x, float g2y, float errsq,
                                           float fxz, float fxz2, float fyz, float fyz2,
                                           float x_, float y_, float d) {
    if (idx < 21) {
        int i = c_hi[idx], j = c_hj[idx];
        float a0 = selJ0(i, fxz, fxz2, x_, y_, d);
        float a1 = selJ1(i, fyz, fyz2, x_, y_, d);
        float b0 = selJ0(j, fxz, fxz2, x_, y_, d);
        float b1 = selJ1(j, fyz, fyz2, x_, y_, d);
        float u  = Mxx * a0 + Mxy * a1;
        float vv = Mxy * a0 + Myy * a1;
        return u * b0 + vv * b1;
    } else if (idx < 27) {
        int j = idx - 21;
        float b0 = selJ0(j, fxz, fxz2, x_, y_, d);
        float b1 = selJ1(j, fyz, fyz2, x_, y_, d);
        return g2x * b0 + g2y * b1;
    } else if (idx == 27) {
        return errsq;
    }
    return 1.0f;
}

// ---------------- main LM accumulation at candidate pose (+ fused solve) ----------------
__global__ void __launch_bounds__(256, 3) k_main(const float* __restrict__ p3D,
                                                 const float* __restrict__ fref,
                                                 const float* __restrict__ Km,
                                                 int N, int iter) {
    int tid = threadIdx.x, lane = tid & 31, warp = tid >> 5;
    int hl = lane & 15;
    int side = lane >> 4;
    int wid = blockIdx.x * 8 + warp;
    const int STRIDE = PGRID * 16;   // points per pass

    float R[9], T[3];
#pragma unroll
    for (int i = 0; i < 9; i++) R[i] = g_Rn[i];
#pragma unroll
    for (int i = 0; i < 3; i++) T[i] = g_tn[i];
    float fx = Km[0], fy = Km[4], cx = Km[2], cy = Km[5];

    const uint4* __restrict__ B = (const uint4*)g_fqH;
    const float4* __restrict__ F4p = (const float4*)fref;

    double a0 = 0.0, a1 = 0.0;
    for (int pb = 2 * wid; pb < N; pb += STRIDE) {
        int pt = pb + side;
        bool vp = (pt < N);
        int ptc = vp ? pt : 0;

        float Px = p3D[3 * ptc], Py = p3D[3 * ptc + 1], Pz = p3D[3 * ptc + 2];
        float x_ = R[0] * Px + R[1] * Py + R[2] * Pz + T[0];
        float y_ = R[3] * Px + R[4] * Py + R[5] * Pz + T[1];
        float d  = R[6] * Px + R[7] * Py + R[8] * Pz + T[2];
        float izd0 = 1.0f / d;
        float px = x_ * izd0 * fx + cx;
        float py = y_ * izd0 * fy + cy;
        if (iter == 0 && hl == 0 && vp) { g_p2init[2 * pt] = px; g_p2init[2 * pt + 1] = py; }
        bool valid = vp && inImage(px, py);
        if (!valid) { px = 256.0f; py = 256.0f; d = 1.0f; }
        float izd = 1.0f / d;

        float x0f = floorf(px), y0f = floorf(py);
        float wx = px - x0f, wy = py - y0f;
        int x0 = (int)x0f, x1 = x0 + 1, y0 = (int)y0f, y1 = y0 + 1;
        int colo[4] = {(x0 - 1) * 16, x0 * 16, x1 * 16, (x1 < 511 ? x1 + 1 : 511) * 16};
        int rowo[4] = {(y0 - 1) * (WW * 16), y0 * (WW * 16), y1 * (WW * 16),
                       (y1 < 511 ? y1 + 1 : 511) * (WW * 16)};

        // separable sobel x bilinear weights
        float Ax[4]  = {1.0f - wx, 2.0f - wx, 1.0f + wx, wx};
        float Bx[4]  = {-(1.0f - wx), -wx, 1.0f - wx, wx};
        float Ay8[4] = {(1.0f - wy) * 0.125f, (2.0f - wy) * 0.125f,
                        (1.0f + wy) * 0.125f, wy * 0.125f};
        float By8[4] = {-(1.0f - wy) * 0.125f, -wy * 0.125f,
                        (1.0f - wy) * 0.125f, wy * 0.125f};
        float fxw0 = 1.0f - wx, fyw0 = 1.0f - wy;

        float2 f2[4], gx2[4], gy2[4];
#pragma unroll
        for (int q = 0; q < 4; q++) {
            f2[q] = make_float2(0.f, 0.f);
            gx2[q] = make_float2(0.f, 0.f);
            gy2[q] = make_float2(0.f, 0.f);
        }
#pragma unroll
        for (int i = 0; i < 4; i++) {
            float2 rx2[4], ra2[4];
#pragma unroll
            for (int q = 0; q < 4; q++) { rx2[q] = make_float2(0.f, 0.f); ra2[q] = make_float2(0.f, 0.f); }
#pragma unroll
            for (int j = 0; j < 4; j++) {
                uint4 raw = __ldg(&B[rowo[i] + colo[j] + hl]);
                float2 p2[4];
                p2[0] = h2f2(raw.x); p2[1] = h2f2(raw.y);
                p2[2] = h2f2(raw.z); p2[3] = h2f2(raw.w);
                float2 bx = bcast2(Bx[j]), ax = bcast2(Ax[j]);
#pragma unroll
                for (int q = 0; q < 4; q++) {
                    rx2[q] = ffma2(bx, p2[q], rx2[q]);
                    ra2[q] = ffma2(ax, p2[q], ra2[q]);
                }
                if ((i == 1 || i == 2) && (j == 1 || j == 2)) {
                    float2 wc = bcast2(((j == 1) ? fxw0 : wx) * ((i == 1) ? fyw0 : wy));
#pragma unroll
                    for (int q = 0; q < 4; q++) f2[q] = ffma2(wc, p2[q], f2[q]);
                }
            }
            float2 ay = bcast2(Ay8[i]), by = bcast2(By8[i]);
#pragma unroll
            for (int q = 0; q < 4; q++) {
                gx2[q] = ffma2(ay, rx2[q], gx2[q]);
                gy2[q] = ffma2(by, ra2[q], gy2[q]);
            }
        }
        float2 r2[4];
        {
            float4 ra4 = __ldg(&F4p[ptc * 32 + 2 * hl]);
            float4 rb4 = __ldg(&F4p[ptc * 32 + 2 * hl + 1]);
            r2[0] = make_float2(ra4.x, ra4.y);
            r2[1] = make_float2(ra4.z, ra4.w);
            r2[2] = make_float2(rb4.x, rb4.y);
            r2[3] = make_float2(rb4.z, rb4.w);
        }

        float2 t2[10];
#pragma unroll
        for (int i = 0; i < 10; i++) t2[i] = make_float2(0.f, 0.f);
#pragma unroll
        for (int q = 0; q < 4; q++) {
            t2[0] = ffma2(f2[q], f2[q], t2[0]);
            t2[1] = ffma2(f2[q], gx2[q], t2[1]);
            t2[2] = ffma2(f2[q], gy2[q], t2[2]);
            t2[3] = ffma2(gx2[q], gx2[q], t2[3]);
            t2[4] = ffma2(gx2[q], gy2[q], t2[4]);
            t2[5] = ffma2(gy2[q], gy2[q], t2[5]);
            t2[6] = ffma2(gx2[q], r2[q], t2[6]);
            t2[7] = ffma2(gy2[q], r2[q], t2[7]);
            t2[8] = ffma2(f2[q], r2[q], t2[8]);
            t2[9] = ffma2(r2[q], r2[q], t2[9]);
        }
        float s[10];
#pragma unroll
        for (int i = 0; i < 10; i++) s[i] = t2[i].x + t2[i].y;
        halfReduce<10>(s);

        float norm  = fmaxf(sqrtf(s[0]), 1e-12f);
        float rnorm = fmaxf(sqrtf(s[9]), 1e-12f);
        float inorm = 1.0f / norm, irn = 1.0f / rnorm;
        float projx = s[1] * inorm, projy = s[2] * inorm;
        float nf2 = s[0] * inorm * inorm;
        float sc  = s[8] * inorm * irn;
        float in2 = inorm * inorm;
        float fac = 2.0f - nf2;
        float Mxx = (s[3] - projx * projx * fac) * in2;
        float Mxy = (s[4] - projx * projy * fac) * in2;
        float Myy = (s[5] - projy * projy * fac) * in2;
        float coef = 1.0f - nf2 + sc;
        float g2x = (projx * coef - s[6] * irn) * inorm;
        float g2y = (projy * coef - s[7] * irn) * inorm;
        float errsq = nf2 - 2.0f * sc + s[9] * irn * irn;

        float fxz = fx * izd, fxz2 = -fx * x_ * izd * izd;
        float fyz = fy * izd, fyz2 = -fy * y_ * izd * izd;
        float vf = valid ? 1.0f : 0.0f;

        a0 += (double)(vf * valForIdx(hl, Mxx, Mxy, Myy, g2x, g2y, errsq,
                                      fxz, fxz2, fyz, fyz2, x_, y_, d));
        if (hl < 13)
            a1 += (double)(vf * valForIdx(hl + 16, Mxx, Mxy, Myy, g2x, g2y, errsq,
                                          fxz, fxz2, fyz, fyz2, x_, y_, d));
    }
    a0 += __shfl_down_sync(0xffffffffu, a0, 16);
    a1 += __shfl_down_sync(0xffffffffu, a1, 16);

    __shared__ double sred[8][29];
    __shared__ bool s_last;
    if (lane < 16) sred[warp][lane] = a0;
    if (lane < 13) sred[warp][16 + lane] = a1;
    __syncthreads();
    if (warp == 0 && lane < 29) {
        double tt = 0.0;
#pragma unroll
        for (int w2i = 0; w2i < 8; w2i++) tt += sred[w2i][lane];
        atomicAdd(&g_acc[lane], tt);
    }
    __syncthreads();
    if (tid == 0) {
        __threadfence();
        unsigned int t = atomicAdd(&g_count, 1u);
        s_last = (t == gridDim.x - 1);
    }
    __syncthreads();
    if (s_last && tid == 0) {
        __threadfence();
        do_solve(iter);
    }
}

// ---------------- trial cost of final candidate c8 ----------------
__global__ void __launch_bounds__(256) k_trial(const float* __restrict__ p3D,
                                               const float* __restrict__ fref,
                                               const float* __restrict__ Km, int N) {
    int tid = threadIdx.x, lane = tid & 31, warp = tid >> 5;
    int hl = lane & 15, side = lane >> 4;
    int wid = blockIdx.x * 8 + warp;
    const int STRIDE = PGRID * 16;

    float R[9], T[3];
#pragma unroll
    for (int i = 0; i < 9; i++) R[i] = g_Rn[i];
#pragma unroll
    for (int i = 0; i < 3; i++) T[i] = g_tn[i];
    float fx = Km[0], fy = Km[4], cx = Km[2], cy = Km[5];

    const uint4* __restrict__ B = (const uint4*)g_fqH;
    const float4* __restrict__ F4p = (const float4*)fref;

    double eD = 0.0, eC = 0.0;
    for (int pb = 2 * wid; pb < N; pb += STRIDE) {
        int pt = pb + side;
        bool vp = (pt < N);
        int ptc = vp ? pt : 0;

        float Px = p3D[3 * ptc], Py = p3D[3 * ptc + 1], Pz = p3D[3 * ptc + 2];
        float x_ = R[0] * Px + R[1] * Py + R[2] * Pz + T[0];
        float y_ = R[3] * Px + R[4] * Py + R[5] * Pz + T[1];
        float d  = R[6] * Px + R[7] * Py + R[8] * Pz + T[2];
        float izd = 1.0f / d;
        float px = x_ * izd * fx + cx;
        float py = y_ * izd * fy + cy;
        bool valid = vp && inImage(px, py);
        if (!valid) { px = 256.0f; py = 256.0f; }

        int o[4]; float w[4];
        bilin4(px, py, o, w);
        float f8[8];
#pragma unroll
        for (int j = 0; j < 8; j++) f8[j] = 0.0f;
#pragma unroll
        for (int k = 0; k < 4; k++) {
            uint4 raw = __ldg(&B[o[k] + hl]);
            float p[8];
            unpack8(raw, p);
#pragma unroll
            for (int j = 0; j < 8; j++) f8[j] += w[k] * p[j];
        }
        float r8[8];
        {
            float4 ra = __ldg(&F4p[ptc * 32 + 2 * hl]);
            float4 rb = __ldg(&F4p[ptc * 32 + 2 * hl + 1]);
            r8[0] = ra.x; r8[1] = ra.y; r8[2] = ra.z; r8[3] = ra.w;
            r8[4] = rb.x; r8[5] = rb.y; r8[6] = rb.z; r8[7] = rb.w;
        }
        float s[3] = {0.0f, 0.0f, 0.0f};
#pragma unroll
        for (int j = 0; j < 8; j++) {
            s[0] += f8[j] * f8[j];
            s[1] += f8[j] * r8[j];
            s[2] += r8[j] * r8[j];
        }
        halfReduce<3>(s);

        float inorm = 1.0f / fmaxf(sqrtf(s[0]), 1e-12f);
        float irn   = 1.0f / fmaxf(sqrtf(s[2]), 1e-12f);
        float errsq = s[0] * inorm * inorm - 2.0f * s[1] * inorm * irn + s[2] * irn * irn;
        float vf = valid ? 1.0f : 0.0f;
        if (hl == 0) {
            eD += (double)(errsq * vf);
            eC += (double)vf;
        }
    }
    eD += __shfl_down_sync(0xffffffffu, eD, 16);
    eC += __shfl_down_sync(0xffffffffu, eC, 16);

    __shared__ double sD[8], sC[8];
    if (lane == 0) { sD[warp] = eD; sC[warp] = eC; }
    __syncthreads();
    if (tid == 0) {
        double a = 0.0, b = 0.0;
#pragma unroll
        for (int i = 0; i < 8; i++) { a += sD[i]; b += sC[i]; }
        atomicAdd(&g_tacc[0], a);
        atomicAdd(&g_tacc[1], b);
    }
}

// ---------------- final costs + output ----------------
__global__ void __launch_bounds__(256) k_final(const float* __restrict__ p3D,
                                               const float* __restrict__ fref,
                                               const float* __restrict__ Km,
                                               int N, float* __restrict__ out) {
    int tid = threadIdx.x, lane = tid & 31, warp = tid >> 5;
    int hl = lane & 15, side = lane >> 4;
    int wid = blockIdx.x * 8 + warp;
    const int STRIDE = PGRID * 16;

    double cn = g_tacc[0] / g_tacc[1];
    bool accPrev = (cn <= g_costbest);
    float R[9], T[3];
#pragma unroll
    for (int i = 0; i < 9; i++) R[i] = accPrev ? g_Rn[i] : g_R[i];
#pragma unroll
    for (int i = 0; i < 3; i++) T[i] = accPrev ? g_tn[i] : g_t[i];
    float fx = Km[0], fy = Km[4], cx = Km[2], cy = Km[5];

    if (blockIdx.x == 0 && tid == 0) {
#pragma unroll
        for (int i = 0; i < 9; i++) out[i] = R[i];
#pragma unroll
        for (int i = 0; i < 3; i++) out[9 + i] = T[i];
    }
    const float NANF = __int_as_float(0x7fc00000);

    const uint4* __restrict__ B = (const uint4*)g_fqH;
    const float4* __restrict__ F4p = (const float4*)fref;

    for (int pb = 2 * wid; pb < N; pb += STRIDE) {
        int pt = pb + side;
        bool vp = (pt < N);
        int ptc = vp ? pt : 0;

        float pix = g_p2init[2 * ptc], piy = g_p2init[2 * ptc + 1];
        float Px = p3D[3 * ptc], Py = p3D[3 * ptc + 1], Pz = p3D[3 * ptc + 2];
        float x_ = R[0] * Px + R[1] * Py + R[2] * Pz + T[0];
        float y_ = R[3] * Px + R[4] * Py + R[5] * Pz + T[1];
        float d  = R[6] * Px + R[7] * Py + R[8] * Pz + T[2];
        float izd = 1.0f / d;
        float pfx = x_ * izd * fx + cx;
        float pfy = y_ * izd * fy + cy;

        bool vi = inImage(pix, piy);
        bool vfv = inImage(pfx, pfy);
        float pixc = vi ? pix : 256.0f, piyc = vi ? piy : 256.0f;
        float pfxc = vfv ? pfx : 256.0f, pfyc = vfv ? pfy : 256.0f;

        int oi[4], of_[4];
        float wi[4], wf[4];
        bilin4(pixc, piyc, oi, wi);
        bilin4(pfxc, pfyc, of_, wf);

        float fi8[8], ff8[8];
#pragma unroll
        for (int j = 0; j < 8; j++) { fi8[j] = 0.0f; ff8[j] = 0.0f; }
#pragma unroll
        for (int k = 0; k < 4; k++) {
            uint4 rawi = __ldg(&B[oi[k] + hl]);
            uint4 rawf = __ldg(&B[of_[k] + hl]);
            float pi[8], pf[8];
            unpack8(rawi, pi);
            unpack8(rawf, pf);
#pragma unroll
            for (int j = 0; j < 8; j++) {
                fi8[j] += wi[k] * pi[j];
                ff8[j] += wf[k] * pf[j];
            }
        }
        float r8[8];
        {
            float4 ra = __ldg(&F4p[ptc * 32 + 2 * hl]);
            float4 rb = __ldg(&F4p[ptc * 32 + 2 * hl + 1]);
            r8[0] = ra.x; r8[1] = ra.y; r8[2] = ra.z; r8[3] = ra.w;
            r8[4] = rb.x; r8[5] = rb.y; r8[6] = rb.z; r8[7] = rb.w;
        }
        float s[5] = {0, 0, 0, 0, 0};
#pragma unroll
        for (int j = 0; j < 8; j++) {
            s[0] += fi8[j] * fi8[j];
            s[1] += fi8[j] * r8[j];
            s[2] += ff8[j] * ff8[j];
            s[3] += ff8[j] * r8[j];
            s[4] += r8[j] * r8[j];
        }
        halfReduce<5>(s);

        if (hl == 0 && vp) {
            float irn = 1.0f / fmaxf(sqrtf(s[4]), 1e-12f);
            float ini = 1.0f / fmaxf(sqrtf(s[0]), 1e-12f);
            float inf_ = 1.0f / fmaxf(sqrtf(s[2]), 1e-12f);
            float rr = s[4] * irn * irn;
            float ci = rr - 2.0f * s[1] * ini * irn + s[0] * ini * ini;
            float cf = rr - 2.0f * s[3] * inf_ * irn + s[2] * inf_ * inf_;
            out[12 + pt]     = vi  ? ci : NANF;
            out[12 + N + pt] = vfv ? cf : NANF;
        }
    }
}

// ---------------- launch ----------------
extern "C" void kernel_launch(void* const* d_in, const int* in_sizes, int n_in,
                              void* d_out, int out_size) {
    const float* p3D  = (const float*)d_in[0];
    const float* fref = (const float*)d_in[1];
    const float* fq   = (const float*)d_in[2];
    const float* Km   = (const float*)d_in[3];
    const float* R0   = (const float*)d_in[4];
    const float* t0   = (const float*)d_in[5];
    float* out = (float*)d_out;
    int N = in_sizes[0] / 3;
    if (N > MAXN) N = MAXN;

    k_init<<<1, 32>>>(R0, t0);
    k_transpose<<<NHW / 64, 256>>>(fq);
    for (int i = 0; i < 8; i++)
        k_main<<<PGRID, 256>>>(p3D, fref, Km, N, i);   // evaluates candidate c_i (c_0 = init)
    k_trial<<<PGRID, 256>>>(p3D, fref, Km, N);         // cost of c8 only
    k_final<<<PGRID, 256>>>(p3D, fref, Km, N, out);
}

// round 12
// speedup vs baseline: 1.7639x; 1.0413x over previous
#include <cuda_runtime.h>
#include <cuda_fp16.h>
#include <math.h>

#define NC   128
#define WW   512
#define HH   512
#define NHW  (HH*WW)
#define MAXN 10000
#define PGRID 444   // exactly 3 blocks/SM x 148 SMs at 80 regs: single co-resident wave

// ---------------- persistent device state ----------------
__device__ __align__(16) __half g_fqH[NC * NHW];  // (pixel, channel) layout, fp16
__device__ float  g_p2init[2 * MAXN];
__device__ double g_acc[29];    // [0..20] Hess uptri, [21..26] Grad, [27] cost, [28] count
__device__ double g_Hsav[27];   // H/G snapshot at last accepted pose
__device__ double g_tacc[2];    // final trial cost sum, count
__device__ double g_costbest;
__device__ float  g_R[9], g_t[3];     // accepted pose
__device__ float  g_Rn[9], g_tn[3];   // eval / candidate pose
__device__ float  g_lam, g_jac[6];
__device__ unsigned int g_count;

__constant__ int c_hi[21] = {0,0,0,0,0,0, 1,1,1,1,1, 2,2,2,2, 3,3,3, 4,4, 5};
__constant__ int c_hj[21] = {0,1,2,3,4,5, 1,2,3,4,5, 2,3,4,5, 3,4,5, 4,5, 5};

// ---------------- helpers ----------------
typedef unsigned long long u64t;

__device__ __forceinline__ float2 ffma2(float2 a, float2 b, float2 c) {
    float2 d;
    asm("fma.rn.f32x2 %0, %1, %2, %3;"
        : "=l"(reinterpret_cast<u64t&>(d))
        : "l"(reinterpret_cast<const u64t&>(a)),
          "l"(reinterpret_cast<const u64t&>(b)),
          "l"(reinterpret_cast<const u64t&>(c)));
    return d;
}
__device__ __forceinline__ float2 bcast2(float w) { return make_float2(w, w); }
__device__ __forceinline__ float2 h2f2(unsigned int h) {
    return __half22float2(*(__half2*)&h);
}

__device__ __forceinline__ void unpack8(uint4 raw, float* p) {
    const __half2* h = (const __half2*)&raw;
#pragma unroll
    for (int j = 0; j < 4; j++) {
        float2 f = __half22float2(h[j]);
        p[2 * j]     = f.x;
        p[2 * j + 1] = f.y;
    }
}

template <int NV>
__device__ __forceinline__ void halfReduce(float* v) {
#pragma unroll
    for (int off = 8; off > 0; off >>= 1)
#pragma unroll
        for (int i = 0; i < NV; i++) v[i] += __shfl_xor_sync(0xffffffffu, v[i], off);
}

__device__ __forceinline__ float selJ0(int k, float fxz, float fxz2, float x, float y, float z) {
    switch (k) {
        case 0: return fxz;
        case 1: return 0.0f;
        case 2: return fxz2;
        case 3: return fxz2 * y;
        case 4: return fxz * z - fxz2 * x;
        default: return -fxz * y;
    }
}
__device__ __forceinline__ float selJ1(int k, float fyz, float fyz2, float x, float y, float z) {
    switch (k) {
        case 0: return 0.0f;
        case 1: return fyz;
        case 2: return fyz2;
        case 3: return -fyz * z + fyz2 * y;
        case 4: return -fyz2 * x;
        default: return fyz * x;
    }
}

__device__ __forceinline__ bool inImage(float px, float py) {
    return (px >= 1.0f) && (px < 511.0f) && (py >= 1.0f) && (py < 511.0f);
}

// bilinear footprint in uint4 (=8 half-channels) units: 16 per pixel
__device__ __forceinline__ void bilin4(float px, float py, int* o, float* w) {
    float x0f = fminf(fmaxf(floorf(px), 0.0f), 511.0f);
    float y0f = fminf(fmaxf(floorf(py), 0.0f), 511.0f);
    float x1f = fminf(x0f + 1.0f, 511.0f);
    float y1f = fminf(y0f + 1.0f, 511.0f);
    float wx = px - x0f, wy = py - y0f;
    int x0 = (int)x0f, x1 = (int)x1f, y0 = (int)y0f, y1 = (int)y1f;
    o[0] = (y0 * WW + x0) * 16;
    o[1] = (y0 * WW + x1) * 16;
    o[2] = (y1 * WW + x0) * 16;
    o[3] = (y1 * WW + x1) * 16;
    w[0] = (1.0f - wx) * (1.0f - wy);
    w[1] = wx * (1.0f - wy);
    w[2] = (1.0f - wx) * wy;
    w[3] = wx * wy;
}

// ---------------- init ----------------
__global__ void k_init(const float* __restrict__ R0, const float* __restrict__ t0) {
    int i = threadIdx.x;
    if (i < 9) { g_R[i] = R0[i]; g_Rn[i] = R0[i]; }
    if (i < 3) { g_t[i] = t0[i]; g_tn[i] = t0[i]; }
    if (i == 0) {
        g_lam = 0.01f; g_costbest = 0.0;
        g_tacc[0] = 0.0; g_tacc[1] = 1.0;
        g_count = 0u;
    }
    if (i < 29) g_acc[i] = 0.0;
}

// ---------------- transpose (C,H,W) f32 -> (H*W, C) f16, vectorized ----------------
__global__ void __launch_bounds__(256) k_transpose(const float* __restrict__ fq) {
    __shared__ float sh[64][NC + 1];
    int pix0 = blockIdx.x * 64;
    int tid = threadIdx.x;
    int px4 = tid & 15;
    int c0 = tid >> 4;
    const float4* __restrict__ fq4 = (const float4*)fq;
#pragma unroll
    for (int cb = 0; cb < NC; cb += 16) {
        int c = cb + c0;
        float4 v = __ldg(&fq4[(size_t)c * (NHW / 4) + (pix0 >> 2) + px4]);
        sh[4 * px4 + 0][c] = v.x;
        sh[4 * px4 + 1][c] = v.y;
        sh[4 * px4 + 2][c] = v.z;
        sh[4 * px4 + 3][c] = v.w;
    }
    __syncthreads();
    int cq = tid & 15;
    int prow = tid >> 4;
    uint4* out4 = (uint4*)g_fqH;
#pragma unroll
    for (int pb = 0; pb < 64; pb += 16) {
        int p = pb + prow;
        const float* row = &sh[p][8 * cq];
        uint4 v;
        __half2 h0 = __floats2half2_rn(row[0], row[1]);
        __half2 h1 = __floats2half2_rn(row[2], row[3]);
        __half2 h2 = __floats2half2_rn(row[4], row[5]);
        __half2 h3 = __floats2half2_rn(row[6], row[7]);
        v.x = *(unsigned int*)&h0;
        v.y = *(unsigned int*)&h1;
        v.z = *(unsigned int*)&h2;
        v.w = *(unsigned int*)&h3;
        out4[(size_t)(pix0 + p) * 16 + cq] = v;
    }
}

// ---------------- fused fp32 solve (one thread of last-arriving block) ----------------
__device__ void do_solve(int iter) {
    volatile double* acc = g_acc;
    double cn = acc[27] / acc[28];
    if (iter == 0) {
        g_costbest = cn;
        const int dix[6] = {0, 6, 11, 15, 18, 20};
#pragma unroll
        for (int i = 0; i < 6; i++) g_jac[i] = 1.0f / (1.0f + sqrtf((float)acc[dix[i]]));
#pragma unroll
        for (int i = 0; i < 27; i++) g_Hsav[i] = acc[i];
    } else {
        bool a = (cn <= g_costbest);
        float l = g_lam * (a ? 0.1f : 10.0f);
        g_lam = fminf(fmaxf(l, 1e-8f), 1e4f);
        if (a) {
            g_costbest = cn;
#pragma unroll
            for (int i = 0; i < 9; i++) g_R[i] = g_Rn[i];
#pragma unroll
            for (int i = 0; i < 3; i++) g_t[i] = g_tn[i];
#pragma unroll
            for (int i = 0; i < 27; i++) g_Hsav[i] = acc[i];
        }
    }

    float jac[6];
#pragma unroll
    for (int i = 0; i < 6; i++) jac[i] = g_jac[i];

    float A[6][7];
    {
        int idx = 0;
#pragma unroll
        for (int i = 0; i < 6; i++)
#pragma unroll
            for (int j = i; j < 6; j++) {
                float v = (float)g_Hsav[idx++] * jac[i] * jac[j];
                A[i][j] = v;
                A[j][i] = v;
            }
    }
    float lam = g_lam;
#pragma unroll
    for (int i = 0; i < 6; i++) {
        float d = A[i][i];
        A[i][i] = d + (d + 1e-9f) * lam;
        A[i][6] = -(float)g_Hsav[21 + i] * jac[i];
    }
    for (int col = 0; col < 6; col++) {
        int piv = col;
        float best = fabsf(A[col][col]);
        for (int r = col + 1; r < 6; r++) {
            float v = fabsf(A[r][col]);
            if (v > best) { best = v; piv = r; }
        }
        if (piv != col)
            for (int j = 0; j < 7; j++) { float t = A[col][j]; A[col][j] = A[piv][j]; A[piv][j] = t; }
        float ip = 1.0f / A[col][col];
        for (int r = col + 1; r < 6; r++) {
            float f = A[r][col] * ip;
            for (int j = col; j < 7; j++) A[r][j] -= f * A[col][j];
        }
    }
    float x[6];
#pragma unroll
    for (int i = 5; i >= 0; i--) {
        float v = A[i][6];
#pragma unroll
        for (int j = 0; j < 6; j++)
            if (j > i) v -= A[i][j] * x[j];
        x[i] = v / A[i][i];
    }
    float delta[6];
#pragma unroll
    for (int i = 0; i < 6; i++) delta[i] = x[i] * jac[i];

    float w0 = delta[3], w1 = delta[4], w2 = delta[5];
    float th2 = w0 * w0 + w1 * w1 + w2 * w2;
    float th = sqrtf(th2);
    float Ac, Bc;
    if (th < 1e-7f) { Ac = 1.0f; Bc = 0.5f; }
    else            { Ac = sinf(th) / th; Bc = (1.0f - cosf(th)) / th2; }
    float Wm[9] = {0.0f, -w2, w1, w2, 0.0f, -w0, -w1, w0, 0.0f};
    float W2[9];
#pragma unroll
    for (int i = 0; i < 3; i++)
#pragma unroll
        for (int j = 0; j < 3; j++) {
            float s2 = 0.0f;
#pragma unroll
            for (int k = 0; k < 3; k++) s2 += Wm[i * 3 + k] * Wm[k * 3 + j];
            W2[i * 3 + j] = s2;
        }
    float dr[9];
#pragma unroll
    for (int i = 0; i < 9; i++)
        dr[i] = ((i % 4) == 0 ? 1.0f : 0.0f) + Ac * Wm[i] + Bc * W2[i];

    float Rl[9], Tl[3];
#pragma unroll
    for (int i = 0; i < 9; i++) Rl[i] = g_R[i];
#pragma unroll
    for (int i = 0; i < 3; i++) Tl[i] = g_t[i];
#pragma unroll
    for (int i = 0; i < 3; i++) {
#pragma unroll
        for (int j = 0; j < 3; j++) {
            float s2 = 0.0f;
#pragma unroll
            for (int k = 0; k < 3; k++) s2 += dr[i * 3 + k] * Rl[k * 3 + j];
            g_Rn[i * 3 + j] = s2;
        }
        g_tn[i] = dr[i * 3] * Tl[0] + dr[i * 3 + 1] * Tl[1] + dr[i * 3 + 2] * Tl[2] + delta[i];
    }
#pragma unroll
    for (int i = 0; i < 29; i++) g_acc[i] = 0.0;
    g_count = 0u;
}

// accumulator slot value (0..28) for one point
__device__ __forceinline__ float valForIdx(int idx, float Mxx, float Mxy, float Myy,
                                           float g2x, float g2y, float errsq,
                                           float fxz, float fxz2, float fyz, float fyz2,
                                           float x_, float y_, float d) {
    if (idx < 21) {
        int i = c_hi[idx], j = c_hj[idx];
        float a0 = selJ0(i, fxz, fxz2, x_, y_, d);
        float a1 = selJ1(i, fyz, fyz2, x_, y_, d);
        float b0 = selJ0(j, fxz, fxz2, x_, y_, d);
        float b1 = selJ1(j, fyz, fyz2, x_, y_, d);
        float u  = Mxx * a0 + Mxy * a1;
        float vv = Mxy * a0 + Myy * a1;
        return u * b0 + vv * b1;
    } else if (idx < 27) {
        int j = idx - 21;
        float b0 = selJ0(j, fxz, fxz2, x_, y_, d);
        float b1 = selJ1(j, fyz, fyz2, x_, y_, d);
        return g2x * b0 + g2y * b1;
    } else if (idx == 27) {
        return errsq;
    }
    return 1.0f;
}

// ---------------- main LM accumulation at candidate pose (+ fused solve) ----------------
__global__ void __launch_bounds__(256, 3) k_main(const float* __restrict__ p3D,
                                                 const float* __restrict__ fref,
                                                 const float* __restrict__ Km,
                                                 int N, int iter) {
    int tid = threadIdx.x, lane = tid & 31, warp = tid >> 5;
    int hl = lane & 15;
    int side = lane >> 4;
    int wid = blockIdx.x * 8 + warp;
    const int STRIDE = PGRID * 16;   // points per pass

    float R[9], T[3];
#pragma unroll
    for (int i = 0; i < 9; i++) R[i] = g_Rn[i];
#pragma unroll
    for (int i = 0; i < 3; i++) T[i] = g_tn[i];
    float fx = Km[0], fy = Km[4], cx = Km[2], cy = Km[5];

    const uint4* __restrict__ B = (const uint4*)g_fqH;
    const float4* __restrict__ F4p = (const float4*)fref;

    double a0 = 0.0, a1 = 0.0;
    for (int pb = 2 * wid; pb < N; pb += STRIDE) {
        int pt = pb + side;
        bool vp = (pt < N);
        int ptc = vp ? pt : 0;

        float Px = p3D[3 * ptc], Py = p3D[3 * ptc + 1], Pz = p3D[3 * ptc + 2];
        float x_ = R[0] * Px + R[1] * Py + R[2] * Pz + T[0];
        float y_ = R[3] * Px + R[4] * Py + R[5] * Pz + T[1];
        float d  = R[6] * Px + R[7] * Py + R[8] * Pz + T[2];
        float izd0 = 1.0f / d;
        float px = x_ * izd0 * fx + cx;
        float py = y_ * izd0 * fy + cy;
        if (iter == 0 && hl == 0 && vp) { g_p2init[2 * pt] = px; g_p2init[2 * pt + 1] = py; }
        bool valid = vp && inImage(px, py);
        if (!valid) { px = 256.0f; py = 256.0f; d = 1.0f; }
        float izd = 1.0f / d;

        float x0f = floorf(px), y0f = floorf(py);
        float wx = px - x0f, wy = py - y0f;
        int x0 = (int)x0f, x1 = x0 + 1, y0 = (int)y0f, y1 = y0 + 1;
        int colo[4] = {(x0 - 1) * 16, x0 * 16, x1 * 16, (x1 < 511 ? x1 + 1 : 511) * 16};
        int rowo[4] = {(y0 - 1) * (WW * 16), y0 * (WW * 16), y1 * (WW * 16),
                       (y1 < 511 ? y1 + 1 : 511) * (WW * 16)};

        // separable sobel x bilinear weights
        float Ax[4]  = {1.0f - wx, 2.0f - wx, 1.0f + wx, wx};
        float Bx[4]  = {-(1.0f - wx), -wx, 1.0f - wx, wx};
        float Ay8[4] = {(1.0f - wy) * 0.125f, (2.0f - wy) * 0.125f,
                        (1.0f + wy) * 0.125f, wy * 0.125f};
        float By8[4] = {-(1.0f - wy) * 0.125f, -wy * 0.125f,
                        (1.0f - wy) * 0.125f, wy * 0.125f};
        float fxw0 = 1.0f - wx, fyw0 = 1.0f - wy;

        float2 f2[4], gx2[4], gy2[4];
#pragma unroll
        for (int q = 0; q < 4; q++) {
            f2[q] = make_float2(0.f, 0.f);
            gx2[q] = make_float2(0.f, 0.f);
            gy2[q] = make_float2(0.f, 0.f);
        }
#pragma unroll
        for (int i = 0; i < 4; i++) {
            float2 rx2[4], ra2[4];
#pragma unroll
            for (int q = 0; q < 4; q++) { rx2[q] = make_float2(0.f, 0.f); ra2[q] = make_float2(0.f, 0.f); }
#pragma unroll
            for (int j = 0; j < 4; j++) {
                uint4 raw = __ldg(&B[rowo[i] + colo[j] + hl]);
                float2 p2[4];
                p2[0] = h2f2(raw.x); p2[1] = h2f2(raw.y);
                p2[2] = h2f2(raw.z); p2[3] = h2f2(raw.w);
                float2 bx = bcast2(Bx[j]), ax = bcast2(Ax[j]);
#pragma unroll
                for (int q = 0; q < 4; q++) {
                    rx2[q] = ffma2(bx, p2[q], rx2[q]);
                    ra2[q] = ffma2(ax, p2[q], ra2[q]);
                }
                if ((i == 1 || i == 2) && (j == 1 || j == 2)) {
                    float2 wc = bcast2(((j == 1) ? fxw0 : wx) * ((i == 1) ? fyw0 : wy));
#pragma unroll
                    for (int q = 0; q < 4; q++) f2[q] = ffma2(wc, p2[q], f2[q]);
                }
            }
            float2 ay = bcast2(Ay8[i]), by = bcast2(By8[i]);
#pragma unroll
            for (int q = 0; q < 4; q++) {
                gx2[q] = ffma2(ay, rx2[q], gx2[q]);
                gy2[q] = ffma2(by, ra2[q], gy2[q]);
            }
        }
        float2 r2[4];
        {
            float4 ra4 = __ldg(&F4p[ptc * 32 + 2 * hl]);
            float4 rb4 = __ldg(&F4p[ptc * 32 + 2 * hl + 1]);
            r2[0] = make_float2(ra4.x, ra4.y);
            r2[1] = make_float2(ra4.z, ra4.w);
            r2[2] = make_float2(rb4.x, rb4.y);
            r2[3] = make_float2(rb4.z, rb4.w);
        }

        float2 t2[10];
#pragma unroll
        for (int i = 0; i < 10; i++) t2[i] = make_float2(0.f, 0.f);
#pragma unroll
        for (int q = 0; q < 4; q++) {
            t2[0] = ffma2(f2[q], f2[q], t2[0]);
            t2[1] = ffma2(f2[q], gx2[q], t2[1]);
            t2[2] = ffma2(f2[q], gy2[q], t2[2]);
            t2[3] = ffma2(gx2[q], gx2[q], t2[3]);
            t2[4] = ffma2(gx2[q], gy2[q], t2[4]);
            t2[5] = ffma2(gy2[q], gy2[q], t2[5]);
            t2[6] = ffma2(gx2[q], r2[q], t2[6]);
            t2[7] = ffma2(gy2[q], r2[q], t2[7]);
            t2[8] = ffma2(f2[q], r2[q], t2[8]);
            t2[9] = ffma2(r2[q], r2[q], t2[9]);
        }
        float s[10];
#pragma unroll
        for (int i = 0; i < 10; i++) s[i] = t2[i].x + t2[i].y;
        halfReduce<10>(s);

        float norm  = fmaxf(sqrtf(s[0]), 1e-12f);
        float rnorm = fmaxf(sqrtf(s[9]), 1e-12f);
        float inorm = 1.0f / norm, irn = 1.0f / rnorm;
        float projx = s[1] * inorm, projy = s[2] * inorm;
        float nf2 = s[0] * inorm * inorm;
        float sc  = s[8] * inorm * irn;
        float in2 = inorm * inorm;
        float fac = 2.0f - nf2;
        float Mxx = (s[3] - projx * projx * fac) * in2;
        float Mxy = (s[4] - projx * projy * fac) * in2;
        float Myy = (s[5] - projy * projy * fac) * in2;
        float coef = 1.0f - nf2 + sc;
        float g2x = (projx * coef - s[6] * irn) * inorm;
        float g2y = (projy * coef - s[7] * irn) * inorm;
        float errsq = nf2 - 2.0f * sc + s[9] * irn * irn;

        float fxz = fx * izd, fxz2 = -fx * x_ * izd * izd;
        float fyz = fy * izd, fyz2 = -fy * y_ * izd * izd;
        float vf = valid ? 1.0f : 0.0f;

        a0 += (double)(vf * valForIdx(hl, Mxx, Mxy, Myy, g2x, g2y, errsq,
                                      fxz, fxz2, fyz, fyz2, x_, y_, d));
        if (hl < 13)
            a1 += (double)(vf * valForIdx(hl + 16, Mxx, Mxy, Myy, g2x, g2y, errsq,
                                          fxz, fxz2, fyz, fyz2, x_, y_, d));
    }
    a0 += __shfl_down_sync(0xffffffffu, a0, 16);
    a1 += __shfl_down_sync(0xffffffffu, a1, 16);

    __shared__ double sred[8][29];
    __shared__ bool s_last;
    if (lane < 16) sred[warp][lane] = a0;
    if (lane < 13) sred[warp][16 + lane] = a1;
    __syncthreads();
    if (warp == 0 && lane < 29) {
        double tt = 0.0;
#pragma unroll
        for (int w2i = 0; w2i < 8; w2i++) tt += sred[w2i][lane];
        atomicAdd(&g_acc[lane], tt);
    }
    __syncthreads();
    if (tid == 0) {
        __threadfence();
        unsigned int t = atomicAdd(&g_count, 1u);
        s_last = (t == gridDim.x - 1);
    }
    __syncthreads();
    if (s_last && tid == 0) {
        __threadfence();
        do_solve(iter);
    }
}

// ---------------- trial cost of final candidate c8 ----------------
__global__ void __launch_bounds__(256) k_trial(const float* __restrict__ p3D,
                                               const float* __restrict__ fref,
                                               const float* __restrict__ Km, int N) {
    int tid = threadIdx.x, lane = tid & 31, warp = tid >> 5;
    int hl = lane & 15, side = lane >> 4;
    int wid = blockIdx.x * 8 + warp;
    const int STRIDE = PGRID * 16;

    float R[9], T[3];
#pragma unroll
    for (int i = 0; i < 9; i++) R[i] = g_Rn[i];
#pragma unroll
    for (int i = 0; i < 3; i++) T[i] = g_tn[i];
    float fx = Km[0], fy = Km[4], cx = Km[2], cy = Km[5];

    const uint4* __restrict__ B = (const uint4*)g_fqH;
    const float4* __restrict__ F4p = (const float4*)fref;

    double eD = 0.0, eC = 0.0;
    for (int pb = 2 * wid; pb < N; pb += STRIDE) {
        int pt = pb + side;
        bool vp = (pt < N);
        int ptc = vp ? pt : 0;

        float Px = p3D[3 * ptc], Py = p3D[3 * ptc + 1], Pz = p3D[3 * ptc + 2];
        float x_ = R[0] * Px + R[1] * Py + R[2] * Pz + T[0];
        float y_ = R[3] * Px + R[4] * Py + R[5] * Pz + T[1];
        float d  = R[6] * Px + R[7] * Py + R[8] * Pz + T[2];
        float izd = 1.0f / d;
        float px = x_ * izd * fx + cx;
        float py = y_ * izd * fy + cy;
        bool valid = vp && inImage(px, py);
        if (!valid) { px = 256.0f; py = 256.0f; }

        int o[4]; float w[4];
        bilin4(px, py, o, w);
        float f8[8];
#pragma unroll
        for (int j = 0; j < 8; j++) f8[j] = 0.0f;
#pragma unroll
        for (int k = 0; k < 4; k++) {
            uint4 raw = __ldg(&B[o[k] + hl]);
            float p[8];
            unpack8(raw, p);
#pragma unroll
            for (int j = 0; j < 8; j++) f8[j] += w[k] * p[j];
        }
        float r8[8];
        {
            float4 ra = __ldg(&F4p[ptc * 32 + 2 * hl]);
            float4 rb = __ldg(&F4p[ptc * 32 + 2 * hl + 1]);
            r8[0] = ra.x; r8[1] = ra.y; r8[2] = ra.z; r8[3] = ra.w;
            r8[4] = rb.x; r8[5] = rb.y; r8[6] = rb.z; r8[7] = rb.w;
        }
        float s[3] = {0.0f, 0.0f, 0.0f};
#pragma unroll
        for (int j = 0; j < 8; j++) {
            s[0] += f8[j] * f8[j];
            s[1] += f8[j] * r8[j];
            s[2] += r8[j] * r8[j];
        }
        halfReduce<3>(s);

        float inorm = 1.0f / fmaxf(sqrtf(s[0]), 1e-12f);
        float irn   = 1.0f / fmaxf(sqrtf(s[2]), 1e-12f);
        float errsq = s[0] * inorm * inorm - 2.0f * s[1] * inorm * irn + s[2] * irn * irn;
        float vf = valid ? 1.0f : 0.0f;
        if (hl == 0) {
            eD += (double)(errsq * vf);
            eC += (double)vf;
        }
    }
    eD += __shfl_down_sync(0xffffffffu, eD, 16);
    eC += __shfl_down_sync(0xffffffffu, eC, 16);

    __shared__ double sD[8], sC[8];
    if (lane == 0) { sD[warp] = eD; sC[warp] = eC; }
    __syncthreads();
    if (tid == 0) {
        double a = 0.0, b = 0.0;
#pragma unroll
        for (int i = 0; i < 8; i++) { a += sD[i]; b += sC[i]; }
        atomicAdd(&g_tacc[0], a);
        atomicAdd(&g_tacc[1], b);
    }
}

// ---------------- final costs + output ----------------
__global__ void __launch_bounds__(256) k_final(const float* __restrict__ p3D,
                                               const float* __restrict__ fref,
                                               const float* __restrict__ Km,
                                               int N, float* __restrict__ out) {
    int tid = threadIdx.x, lane = tid & 31, warp = tid >> 5;
    int hl = lane & 15, side = lane >> 4;
    int wid = blockIdx.x * 8 + warp;
    const int STRIDE = PGRID * 16;

    double cn = g_tacc[0] / g_tacc[1];
    bool accPrev = (cn <= g_costbest);
    float R[9], T[3];
#pragma unroll
    for (int i = 0; i < 9; i++) R[i] = accPrev ? g_Rn[i] : g_R[i];
#pragma unroll
    for (int i = 0; i < 3; i++) T[i] = accPrev ? g_tn[i] : g_t[i];
    float fx = Km[0], fy = Km[4], cx = Km[2], cy = Km[5];

    if (blockIdx.x == 0 && tid == 0) {
#pragma unroll
        for (int i = 0; i < 9; i++) out[i] = R[i];
#pragma unroll
        for (int i = 0; i < 3; i++) out[9 + i] = T[i];
    }
    const float NANF = __int_as_float(0x7fc00000);

    const uint4* __restrict__ B = (const uint4*)g_fqH;
    const float4* __restrict__ F4p = (const float4*)fref;

    for (int pb = 2 * wid; pb < N; pb += STRIDE) {
        int pt = pb + side;
        bool vp = (pt < N);
        int ptc = vp ? pt : 0;

        float pix = g_p2init[2 * ptc], piy = g_p2init[2 * ptc + 1];
        float Px = p3D[3 * ptc], Py = p3D[3 * ptc + 1], Pz = p3D[3 * ptc + 2];
        float x_ = R[0] * Px + R[1] * Py + R[2] * Pz + T[0];
        float y_ = R[3] * Px + R[4] * Py + R[5] * Pz + T[1];
        float d  = R[6] * Px + R[7] * Py + R[8] * Pz + T[2];
        float izd = 1.0f / d;
        float pfx = x_ * izd * fx + cx;
        float pfy = y_ * izd * fy + cy;

        bool vi = inImage(pix, piy);
        bool vfv = inImage(pfx, pfy);
        float pixc = vi ? pix : 256.0f, piyc = vi ? piy : 256.0f;
        float pfxc = vfv ? pfx : 256.0f, pfyc = vfv ? pfy : 256.0f;

        int oi[4], of_[4];
        float wi[4], wf[4];
        bilin4(pixc, piyc, oi, wi);
        bilin4(pfxc, pfyc, of_, wf);

        float fi8[8], ff8[8];
#pragma unroll
        for (int j = 0; j < 8; j++) { fi8[j] = 0.0f; ff8[j] = 0.0f; }
#pragma unroll
        for (int k = 0; k < 4; k++) {
            uint4 rawi = __ldg(&B[oi[k] + hl]);
            uint4 rawf = __ldg(&B[of_[k] + hl]);
            float pi[8], pf[8];
            unpack8(rawi, pi);
            unpack8(rawf, pf);
#pragma unroll
            for (int j = 0; j < 8; j++) {
                fi8[j] += wi[k] * pi[j];
                ff8[j] += wf[k] * pf[j];
            }
        }
        float r8[8];
        {
            float4 ra = __ldg(&F4p[ptc * 32 + 2 * hl]);
            float4 rb = __ldg(&F4p[ptc * 32 + 2 * hl + 1]);
            r8[0] = ra.x; r8[1] = ra.y; r8[2] = ra.z; r8[3] = ra.w;
            r8[4] = rb.x; r8[5] = rb.y; r8[6] = rb.z; r8[7] = rb.w;
        }
        float s[5] = {0, 0, 0, 0, 0};
#pragma unroll
        for (int j = 0; j < 8; j++) {
            s[0] += fi8[j] * fi8[j];
            s[1] += fi8[j] * r8[j];
            s[2] += ff8[j] * ff8[j];
            s[3] += ff8[j] * r8[j];
            s[4] += r8[j] * r8[j];
        }
        halfReduce<5>(s);

        if (hl == 0 && vp) {
            float irn = 1.0f / fmaxf(sqrtf(s[4]), 1e-12f);
            float ini = 1.0f / fmaxf(sqrtf(s[0]), 1e-12f);
            float inf_ = 1.0f / fmaxf(sqrtf(s[2]), 1e-12f);
            float rr = s[4] * irn * irn;
            float ci = rr - 2.0f * s[1] * ini * irn + s[0] * ini * ini;
            float cf = rr - 2.0f * s[3] * inf_ * irn + s[2] * inf_ * inf_;
            out[12 + pt]     = vi  ? ci : NANF;
            out[12 + N + pt] = vfv ? cf : NANF;
        }
    }
}

// ---------------- launch ----------------
extern "C" void kernel_launch(void* const* d_in, const int* in_sizes, int n_in,
                              void* d_out, int out_size) {
    const float* p3D  = (const float*)d_in[0];
    const float* fref = (const float*)d_in[1];
    const float* fq   = (const float*)d_in[2];
    const float* Km   = (const float*)d_in[3];
    const float* R0   = (const float*)d_in[4];
    const float* t0   = (const float*)d_in[5];
    float* out = (float*)d_out;
    int N = in_sizes[0] / 3;
    if (N > MAXN) N = MAXN;

    k_init<<<1, 32>>>(R0, t0);
    k_transpose<<<NHW / 64, 256>>>(fq);
    for (int i = 0; i < 8; i++)
        k_main<<<PGRID, 256>>>(p3D, fref, Km, N, i);   // evaluates candidate c_i (c_0 = init)
    k_trial<<<PGRID, 256>>>(p3D, fref, Km, N);         // cost of c8 only
    k_final<<<PGRID, 256>>>(p3D, fref, Km, N, out);
}